// round 1
// baseline (speedup 1.0000x reference)
#include <cuda_runtime.h>
#include <math.h>

// ---------------- problem constants ----------------
#define NROWS 8192     // B*T = 64*128
#define DDIM  1024     // input feature dim
#define EDIM  2048     // encoder dim
#define CDDIM 256      // code dim
#define NCODE 1024     // num codes

// output layout (fp32 concat in reference return order)
#define OFF_Q     0
#define OFF_LOSS  2097152
#define OFF_PERP  2097153
#define OFF_ENC   2097154
#define OFF_IDX   10485762
#define FULL_SIZE 10493954

// ---------------- scratch (device globals; no runtime alloc) ----------------
__device__ float g_H1[(size_t)NROWS * EDIM];     // gelu(states @ W_s + b)
__device__ float g_H2[(size_t)NROWS * EDIM];     // gelu(next   @ W_s + b)
__device__ float g_latent[(size_t)NROWS * CDDIM];
__device__ float g_cnorm[NCODE];
__device__ float g_pval[NROWS * 8];              // per (row, code-tile) partial min
__device__ int   g_pidx[NROWS * 8];
__device__ int   g_counts[NCODE];
__device__ float g_loss_sum;

// ---------------- helpers ----------------
__device__ __forceinline__ float gelu_tanh(float x) {
    float x3 = x * x * x;
    float t  = tanhf(0.7978845608028654f * (x + 0.044715f * x3));
    return 0.5f * x * (1.0f + t);
}

// ---------------- zero per-launch accumulators ----------------
__global__ void k_zero() {
    int t = threadIdx.x;
    if (t < NCODE) g_counts[t] = 0;
    if (t == 0)    g_loss_sum = 0.0f;
}

// ---------------- codebook row squared norms ----------------
__global__ void k_cnorm(const float* __restrict__ cb) {
    int c = blockIdx.x * blockDim.x + threadIdx.x;
    if (c < NCODE) {
        float s = 0.0f;
        const float* row = cb + (size_t)c * CDDIM;
        #pragma unroll 8
        for (int k = 0; k < CDDIM; k++) { float v = row[k]; s += v * v; }
        g_cnorm[c] = s;
    }
}

// ---------------- GEMM1: H = gelu(A @ W_s + b_s), A in {states,next_states} ----------------
// M=8192, N=2048, K=1024. 128x128x8 tile, 256 threads, 8x8 per thread.
__global__ __launch_bounds__(256) void k_enc(const float* __restrict__ S,
                                             const float* __restrict__ NS,
                                             const float* __restrict__ W,
                                             const float* __restrict__ bias) {
    const float* A = blockIdx.z ? NS : S;
    float*       C = blockIdx.z ? g_H2 : g_H1;
    const int m0 = blockIdx.y * 128, n0 = blockIdx.x * 128;

    __shared__ __align__(16) float As[8][128];
    __shared__ __align__(16) float Bs[8][128];

    const int tid = threadIdx.x;
    const int tx = tid & 15, ty = tid >> 4;
    const int arow = tid >> 1,  acol4 = (tid & 1) * 4;
    const int brow = tid >> 5,  bcol4 = (tid & 31) * 4;

    float acc[8][8] = {};

    for (int k0 = 0; k0 < DDIM; k0 += 8) {
        float4 av = *(const float4*)(A + (size_t)(m0 + arow) * DDIM + k0 + acol4);
        As[acol4 + 0][arow] = av.x; As[acol4 + 1][arow] = av.y;
        As[acol4 + 2][arow] = av.z; As[acol4 + 3][arow] = av.w;
        *(float4*)&Bs[brow][bcol4] =
            *(const float4*)(W + (size_t)(k0 + brow) * EDIM + n0 + bcol4);
        __syncthreads();
        #pragma unroll
        for (int k = 0; k < 8; k++) {
            float4 a0 = *(float4*)&As[k][ty * 8];
            float4 a1 = *(float4*)&As[k][ty * 8 + 4];
            float4 b0 = *(float4*)&Bs[k][tx * 8];
            float4 b1 = *(float4*)&Bs[k][tx * 8 + 4];
            float a[8] = {a0.x,a0.y,a0.z,a0.w,a1.x,a1.y,a1.z,a1.w};
            float b[8] = {b0.x,b0.y,b0.z,b0.w,b1.x,b1.y,b1.z,b1.w};
            #pragma unroll
            for (int i = 0; i < 8; i++)
                #pragma unroll
                for (int j = 0; j < 8; j++) acc[i][j] += a[i] * b[j];
        }
        __syncthreads();
    }
    #pragma unroll
    for (int i = 0; i < 8; i++) {
        int row = m0 + ty * 8 + i;
        #pragma unroll
        for (int j = 0; j < 8; j++) {
            int col = n0 + tx * 8 + j;
            C[(size_t)row * EDIM + col] = gelu_tanh(acc[i][j] + bias[col]);
        }
    }
}

// ---------------- GEMM2: latent = [H1|H2] @ W_p + b_p ----------------
// M=8192, N=256, K=4096 (first 2048 from H1, rest from H2)
__global__ __launch_bounds__(256) void k_pol(const float* __restrict__ W,
                                             const float* __restrict__ bias) {
    const int m0 = blockIdx.y * 128, n0 = blockIdx.x * 128;

    __shared__ __align__(16) float As[8][128];
    __shared__ __align__(16) float Bs[8][128];

    const int tid = threadIdx.x;
    const int tx = tid & 15, ty = tid >> 4;
    const int arow = tid >> 1,  acol4 = (tid & 1) * 4;
    const int brow = tid >> 5,  bcol4 = (tid & 31) * 4;

    float acc[8][8] = {};

    for (int k0 = 0; k0 < 2 * EDIM; k0 += 8) {
        const float* A = (k0 < EDIM) ? g_H1 : g_H2;
        int ac = (k0 < EDIM) ? k0 : (k0 - EDIM);
        float4 av = *(const float4*)(A + (size_t)(m0 + arow) * EDIM + ac + acol4);
        As[acol4 + 0][arow] = av.x; As[acol4 + 1][arow] = av.y;
        As[acol4 + 2][arow] = av.z; As[acol4 + 3][arow] = av.w;
        *(float4*)&Bs[brow][bcol4] =
            *(const float4*)(W + (size_t)(k0 + brow) * CDDIM + n0 + bcol4);
        __syncthreads();
        #pragma unroll
        for (int k = 0; k < 8; k++) {
            float4 a0 = *(float4*)&As[k][ty * 8];
            float4 a1 = *(float4*)&As[k][ty * 8 + 4];
            float4 b0 = *(float4*)&Bs[k][tx * 8];
            float4 b1 = *(float4*)&Bs[k][tx * 8 + 4];
            float a[8] = {a0.x,a0.y,a0.z,a0.w,a1.x,a1.y,a1.z,a1.w};
            float b[8] = {b0.x,b0.y,b0.z,b0.w,b1.x,b1.y,b1.z,b1.w};
            #pragma unroll
            for (int i = 0; i < 8; i++)
                #pragma unroll
                for (int j = 0; j < 8; j++) acc[i][j] += a[i] * b[j];
        }
        __syncthreads();
    }
    #pragma unroll
    for (int i = 0; i < 8; i++) {
        int row = m0 + ty * 8 + i;
        #pragma unroll
        for (int j = 0; j < 8; j++) {
            int col = n0 + tx * 8 + j;
            g_latent[(size_t)row * CDDIM + col] = acc[i][j] + bias[col];
        }
    }
}

// ---------------- scores: per row partial argmin of (||c||^2 - 2 x.c) over 128-code tile --------
// M=8192, N=1024 (codes), K=256
__global__ __launch_bounds__(256) void k_score(const float* __restrict__ CB) {
    const int m0 = blockIdx.y * 128, c0 = blockIdx.x * 128;

    __shared__ __align__(16) float As[8][128];
    __shared__ __align__(16) float Bs[8][128];
    __shared__ float rv[128][16];
    __shared__ int   ri[128][16];

    const int tid = threadIdx.x;
    const int tx = tid & 15, ty = tid >> 4;
    const int arow = tid >> 1,  acol4 = (tid & 1) * 4;

    float acc[8][8] = {};

    for (int k0 = 0; k0 < CDDIM; k0 += 8) {
        float4 av = *(const float4*)(g_latent + (size_t)(m0 + arow) * CDDIM + k0 + acol4);
        As[acol4 + 0][arow] = av.x; As[acol4 + 1][arow] = av.y;
        As[acol4 + 2][arow] = av.z; As[acol4 + 3][arow] = av.w;
        // codebook row (c0+arow), cols k0+acol4.. -> transposed into Bs[k][c]
        float4 bv = *(const float4*)(CB + (size_t)(c0 + arow) * CDDIM + k0 + acol4);
        Bs[acol4 + 0][arow] = bv.x; Bs[acol4 + 1][arow] = bv.y;
        Bs[acol4 + 2][arow] = bv.z; Bs[acol4 + 3][arow] = bv.w;
        __syncthreads();
        #pragma unroll
        for (int k = 0; k < 8; k++) {
            float4 a0 = *(float4*)&As[k][ty * 8];
            float4 a1 = *(float4*)&As[k][ty * 8 + 4];
            float4 b0 = *(float4*)&Bs[k][tx * 8];
            float4 b1 = *(float4*)&Bs[k][tx * 8 + 4];
            float a[8] = {a0.x,a0.y,a0.z,a0.w,a1.x,a1.y,a1.z,a1.w};
            float b[8] = {b0.x,b0.y,b0.z,b0.w,b1.x,b1.y,b1.z,b1.w};
            #pragma unroll
            for (int i = 0; i < 8; i++)
                #pragma unroll
                for (int j = 0; j < 8; j++) acc[i][j] += a[i] * b[j];
        }
        __syncthreads();
    }

    #pragma unroll
    for (int i = 0; i < 8; i++) {
        float bv = INFINITY; int bi = 0x7fffffff;
        #pragma unroll
        for (int j = 0; j < 8; j++) {
            int c = c0 + tx * 8 + j;
            float s = g_cnorm[c] - 2.0f * acc[i][j];
            if (s < bv) { bv = s; bi = c; }
        }
        rv[ty * 8 + i][tx] = bv;
        ri[ty * 8 + i][tx] = bi;
    }
    __syncthreads();
    if (tid < 128) {
        float v = rv[tid][0]; int ii = ri[tid][0];
        #pragma unroll
        for (int t = 1; t < 16; t++) {
            float ov = rv[tid][t]; int oi = ri[tid][t];
            if (ov < v || (ov == v && oi < ii)) { v = ov; ii = oi; }
        }
        g_pval[(m0 + tid) * 8 + blockIdx.x] = v;
        g_pidx[(m0 + tid) * 8 + blockIdx.x] = ii;
    }
}

// ---------------- finalize: one warp per row ----------------
__global__ __launch_bounds__(256) void k_final(const float* __restrict__ CB,
                                               float* __restrict__ out, int full) {
    const int warp = threadIdx.x >> 5, lane = threadIdx.x & 31;
    const int row = blockIdx.x * 8 + warp;

    float v = INFINITY; int ii = 0x7fffffff;
    if (lane < 8) { v = g_pval[row * 8 + lane]; ii = g_pidx[row * 8 + lane]; }
    #pragma unroll
    for (int off = 16; off > 0; off >>= 1) {
        float ov = __shfl_down_sync(0xffffffffu, v, off);
        int   oi = __shfl_down_sync(0xffffffffu, ii, off);
        if (ov < v || (ov == v && oi < ii)) { v = ov; ii = oi; }
    }
    int idx = __shfl_sync(0xffffffffu, ii, 0);

    // quantize output + commitment-loss partial
    float ls = 0.0f;
    for (int j = lane; j < CDDIM; j += 32) {
        float c = CB[(size_t)idx * CDDIM + j];
        float l = g_latent[(size_t)row * CDDIM + j];
        out[OFF_Q + (size_t)row * CDDIM + j] = c;
        float d = c - l; ls += d * d;
    }
    #pragma unroll
    for (int off = 16; off > 0; off >>= 1)
        ls += __shfl_down_sync(0xffffffffu, ls, off);
    if (lane == 0) {
        atomicAdd(&g_loss_sum, ls);
        atomicAdd(&g_counts[idx], 1);
    }
    if (full) {
        float* enc = out + OFF_ENC + (size_t)row * NCODE;
        for (int j = lane; j < NCODE; j += 32) enc[j] = (j == idx) ? 1.0f : 0.0f;
        if (lane == 0) out[OFF_IDX + row] = (float)idx;
    }
}

// ---------------- scalars: loss + perplexity ----------------
__global__ void k_scalar(float* __restrict__ out) {
    __shared__ float sh[256];
    int t = threadIdx.x;
    float e = 0.0f;
    for (int c = t; c < NCODE; c += 256) {
        float p = (float)g_counts[c] * (1.0f / (float)NROWS);
        e += p * logf(p + 1e-10f);
    }
    sh[t] = e;
    __syncthreads();
    for (int s = 128; s > 0; s >>= 1) {
        if (t < s) sh[t] += sh[t + s];
        __syncthreads();
    }
    if (t == 0) {
        out[OFF_LOSS] = 0.25f * g_loss_sum / ((float)NROWS * (float)CDDIM);
        out[OFF_PERP] = expf(-sh[0]);
    }
}

// ---------------- launch ----------------
extern "C" void kernel_launch(void* const* d_in, const int* in_sizes, int n_in,
                              void* d_out, int out_size) {
    const float* states      = (const float*)d_in[0];
    const float* next_states = (const float*)d_in[1];
    const float* W_s         = (const float*)d_in[2];
    const float* b_s         = (const float*)d_in[3];
    const float* W_p         = (const float*)d_in[4];
    const float* b_p         = (const float*)d_in[5];
    const float* codebook    = (const float*)d_in[6];
    float* out = (float*)d_out;
    int full = (out_size >= OFF_ENC) ? 1 : 0;

    k_zero<<<1, 1024>>>();
    k_cnorm<<<4, 256>>>(codebook);
    k_enc<<<dim3(EDIM / 128, NROWS / 128, 2), 256>>>(states, next_states, W_s, b_s);
    k_pol<<<dim3(CDDIM / 128, NROWS / 128), 256>>>(W_p, b_p);
    k_score<<<dim3(NCODE / 128, NROWS / 128), 256>>>(codebook);
    k_final<<<NROWS / 8, 256>>>(codebook, out, full);
    if (full) k_scalar<<<1, 256>>>(out);
}

// round 4
// speedup vs baseline: 1.0694x; 1.0694x over previous
#include <cuda_runtime.h>
#include <math.h>
#include <stdint.h>

// ---------------- problem constants ----------------
#define NROWS 8192     // B*T
#define DDIM  1024
#define EDIM  2048
#define CDDIM 256
#define NCODE 1024

// output layout (fp32 concat in reference return order)
#define OFF_Q     0
#define OFF_LOSS  2097152
#define OFF_PERP  2097153
#define OFF_ENC   2097154
#define OFF_IDX   10485762

// ---------------- scratch ----------------
__device__ float g_H1[(size_t)NROWS * EDIM];
__device__ float g_H2[(size_t)NROWS * EDIM];
__device__ float g_latent[(size_t)NROWS * CDDIM];
__device__ float g_cnorm[NCODE];
__device__ float g_pval[(size_t)NROWS * 32];
__device__ int   g_pidx[(size_t)NROWS * 32];
__device__ int   g_counts[NCODE];
__device__ float g_loss_sum;

// ---------------- helpers ----------------
// tf32 round: result is a b32 register holding an fp32-compatible bit pattern
__device__ __forceinline__ uint32_t tf32r(float a) {
    uint32_t h;
    asm("cvt.rna.tf32.f32 %0, %1;" : "=r"(h) : "f"(a));
    return h;
}

// D += A*B, m16n8k8 tf32. A row-major frags, B col-major frags.
// a0:(g,t) a1:(g+8,t) a2:(g,t+4) a3:(g+8,t+4); b0:(k=t,n=g) b1:(k=t+4,n=g)
// c0:(g,2t) c1:(g,2t+1) c2:(g+8,2t) c3:(g+8,2t+1)
__device__ __forceinline__ void mma8(float* c, const uint32_t* a, const uint32_t* b) {
    asm volatile(
        "mma.sync.aligned.m16n8k8.row.col.f32.tf32.tf32.f32 "
        "{%0,%1,%2,%3}, {%4,%5,%6,%7}, {%8,%9}, {%0,%1,%2,%3};"
        : "+f"(c[0]), "+f"(c[1]), "+f"(c[2]), "+f"(c[3])
        : "r"(a[0]), "r"(a[1]), "r"(a[2]), "r"(a[3]), "r"(b[0]), "r"(b[1]));
}

__device__ __forceinline__ float gelu_tanh(float x) {
    float x3 = x * x * x;
    float t  = tanhf(0.7978845608028654f * (x + 0.044715f * x3));
    return 0.5f * x * (1.0f + t);
}

// ---------------- main GEMM kernel ----------------
// MODE 0: H = gelu(A @ W_s + b_s)   (A = states or next_states by blockIdx.z)
// MODE 1: latent = [H1|H2] @ W_p + b_p
// MODE 2: scores = latent . codebook^T  -> per-warp partial argmin
// CTA tile: M_CTA x 128, K-chunk 32, 8 warps (2m x 4n), warp tile (M_CTA/2) x 32.
template <int MODE, int M_CTA, int KTOT>
__global__ void __launch_bounds__(256, 1) gemm_mma(
    const float* __restrict__ A0, const float* __restrict__ A1,
    const float* __restrict__ Bsrc, const float* __restrict__ bias)
{
    extern __shared__ uint32_t smu[];
    constexpr int ASZ = M_CTA * 32;       // words per A buffer (hi or lo)
    constexpr int BSZ = 128 * 32;
    constexpr int STG = 2 * ASZ + 2 * BSZ;
    constexpr int NCH = KTOT / 32;
    constexpr int MFR = M_CTA / 32;       // 16-row m-frags per warp
    constexpr int TPR = 256 / M_CTA;      // threads per A row for global load
    constexpr int AF4 = 8 / TPR;          // float4s per thread for A

    const int tid  = threadIdx.x;
    const int wid  = tid >> 5, lane = tid & 31;
    const int wm   = (wid & 1) * (M_CTA / 2);
    const int wn   = (wid >> 1) * 32;
    const int lt   = lane & 3, lg = lane >> 2;

    const int m0 = blockIdx.y * M_CTA, n0 = blockIdx.x * 128;

    // global-load index assignments
    const int arow = tid / TPR;
    const int akb  = (tid % TPR) * (32 / TPR);
    const int bk   = tid >> 3;            // MODE 0/1 (weights [k][n])
    const int bnb  = (tid & 7) * 16;
    const int brow = tid >> 1;            // MODE 2 (codebook [n][k])
    const int bkb  = (tid & 1) * 16;

    float acc[MFR][4][4];
    #pragma unroll
    for (int i = 0; i < MFR; i++)
        #pragma unroll
        for (int j = 0; j < 4; j++)
            #pragma unroll
            for (int e = 0; e < 4; e++) acc[i][j][e] = 0.0f;

    float4 pa[AF4], pb[4];

    auto loadA = [&](int c) {
        const int k0 = c * 32;
        const float* src;
        if (MODE == 0)
            src = (blockIdx.z ? A1 : A0) + (size_t)(m0 + arow) * DDIM + k0;
        else if (MODE == 1)
            src = (k0 < EDIM) ? (g_H1 + (size_t)(m0 + arow) * EDIM + k0)
                              : (g_H2 + (size_t)(m0 + arow) * EDIM + (k0 - EDIM));
        else
            src = g_latent + (size_t)(m0 + arow) * CDDIM + k0;
        #pragma unroll
        for (int j = 0; j < AF4; j++) pa[j] = *(const float4*)(src + akb + 4 * j);
    };

    auto loadB = [&](int c) {
        const int k0 = c * 32;
        if (MODE == 2) {
            const float* src = Bsrc + (size_t)(n0 + brow) * CDDIM + k0 + bkb;
            #pragma unroll
            for (int j = 0; j < 4; j++) pb[j] = *(const float4*)(src + 4 * j);
        } else {
            const int ldb = (MODE == 0) ? EDIM : CDDIM;
            const float* src = Bsrc + (size_t)(k0 + bk) * ldb + n0 + bnb;
            #pragma unroll
            for (int j = 0; j < 4; j++) pb[j] = *(const float4*)(src + 4 * j);
        }
    };

    auto storeA = [&](int stg) {
        uint32_t* Ah = smu + stg * STG;
        uint32_t* Al = Ah + ASZ;
        #pragma unroll
        for (int j = 0; j < AF4; j++) {
            float v[4] = {pa[j].x, pa[j].y, pa[j].z, pa[j].w};
            #pragma unroll
            for (int jj = 0; jj < 4; jj++) {
                const int k = akb + 4 * j + jj;
                uint32_t h = tf32r(v[jj]);
                uint32_t l = tf32r(v[jj] - __uint_as_float(h));
                int off = k * M_CTA + (arow ^ ((k & 3) << 3));
                Ah[off] = h; Al[off] = l;
            }
        }
    };

    auto storeB = [&](int stg) {
        uint32_t* Bh = smu + stg * STG + 2 * ASZ;
        uint32_t* Bl = Bh + BSZ;
        if (MODE == 2) {
            #pragma unroll
            for (int j = 0; j < 4; j++) {
                float v[4] = {pb[j].x, pb[j].y, pb[j].z, pb[j].w};
                #pragma unroll
                for (int jj = 0; jj < 4; jj++) {
                    const int k = bkb + 4 * j + jj;
                    uint32_t h = tf32r(v[jj]);
                    uint32_t l = tf32r(v[jj] - __uint_as_float(h));
                    int off = k * 128 + (brow ^ ((k & 3) << 3));
                    Bh[off] = h; Bl[off] = l;
                }
            }
        } else {
            const int x = (bk & 3) << 3;
            #pragma unroll
            for (int j = 0; j < 4; j++) {
                float v[4] = {pb[j].x, pb[j].y, pb[j].z, pb[j].w};
                uint4 h4, l4;
                h4.x = tf32r(v[0]); l4.x = tf32r(v[0] - __uint_as_float(h4.x));
                h4.y = tf32r(v[1]); l4.y = tf32r(v[1] - __uint_as_float(h4.y));
                h4.z = tf32r(v[2]); l4.z = tf32r(v[2] - __uint_as_float(h4.z));
                h4.w = tf32r(v[3]); l4.w = tf32r(v[3] - __uint_as_float(h4.w));
                int off = bk * 128 + ((bnb + 4 * j) ^ x);
                *(uint4*)&Bh[off] = h4;
                *(uint4*)&Bl[off] = l4;
            }
        }
    };

    auto compute = [&](int stg) {
        const uint32_t* Ah = smu + stg * STG;
        const uint32_t* Al = Ah + ASZ;
        const uint32_t* Bh = Al + ASZ;
        const uint32_t* Bl = Bh + BSZ;
        #pragma unroll
        for (int s = 0; s < 4; s++) {
            const int kb = s * 8 + lt;
            const int xs = lt << 3;
            uint32_t ah[MFR][4], al[MFR][4], bh[4][2], bl[4][2];
            #pragma unroll
            for (int mt = 0; mt < MFR; mt++) {
                const int m = wm + mt * 16 + lg;
                const int i0 = kb * M_CTA + (m ^ xs);
                const int i1 = kb * M_CTA + ((m + 8) ^ xs);
                ah[mt][0] = Ah[i0];
                ah[mt][1] = Ah[i1];
                ah[mt][2] = Ah[i0 + 4 * M_CTA];
                ah[mt][3] = Ah[i1 + 4 * M_CTA];
                al[mt][0] = Al[i0];
                al[mt][1] = Al[i1];
                al[mt][2] = Al[i0 + 4 * M_CTA];
                al[mt][3] = Al[i1 + 4 * M_CTA];
            }
            #pragma unroll
            for (int nt = 0; nt < 4; nt++) {
                const int n = wn + nt * 8 + lg;
                const int j0 = kb * 128 + (n ^ xs);
                bh[nt][0] = Bh[j0];
                bh[nt][1] = Bh[j0 + 4 * 128];
                bl[nt][0] = Bl[j0];
                bl[nt][1] = Bl[j0 + 4 * 128];
            }
            #pragma unroll
            for (int mt = 0; mt < MFR; mt++)
                #pragma unroll
                for (int nt = 0; nt < 4; nt++) {
                    mma8(acc[mt][nt], ah[mt], bh[nt]);   // hi*hi
                    mma8(acc[mt][nt], ah[mt], bl[nt]);   // hi*lo
                    mma8(acc[mt][nt], al[mt], bh[nt]);   // lo*hi
                }
        }
    };

    // ---- pipelined mainloop ----
    loadA(0); loadB(0);
    storeA(0); storeB(0);
    __syncthreads();
    for (int c = 0; c < NCH; c++) {
        if (c + 1 < NCH) { loadA(c + 1); loadB(c + 1); }
        compute(c & 1);
        if (c + 1 < NCH) {
            storeA((c + 1) & 1); storeB((c + 1) & 1);
            __syncthreads();
        }
    }

    // ---- epilogue ----
    if (MODE == 0) {
        float* C = blockIdx.z ? g_H2 : g_H1;
        #pragma unroll
        for (int mt = 0; mt < MFR; mt++)
            #pragma unroll
            for (int h = 0; h < 2; h++) {
                const int row = m0 + wm + mt * 16 + lg + h * 8;
                float* cr = C + (size_t)row * EDIM + n0;
                #pragma unroll
                for (int nt = 0; nt < 4; nt++) {
                    const int col = wn + nt * 8 + 2 * lt;
                    float2 o;
                    o.x = gelu_tanh(acc[mt][nt][h * 2 + 0] + bias[n0 + col]);
                    o.y = gelu_tanh(acc[mt][nt][h * 2 + 1] + bias[n0 + col + 1]);
                    *(float2*)(cr + col) = o;
                }
            }
    } else if (MODE == 1) {
        #pragma unroll
        for (int mt = 0; mt < MFR; mt++)
            #pragma unroll
            for (int h = 0; h < 2; h++) {
                const int row = m0 + wm + mt * 16 + lg + h * 8;
                float* cr = g_latent + (size_t)row * CDDIM + n0;
                #pragma unroll
                for (int nt = 0; nt < 4; nt++) {
                    const int col = wn + nt * 8 + 2 * lt;
                    float2 o;
                    o.x = acc[mt][nt][h * 2 + 0] + bias[n0 + col];
                    o.y = acc[mt][nt][h * 2 + 1] + bias[n0 + col + 1];
                    *(float2*)(cr + col) = o;
                }
            }
    } else {
        #pragma unroll
        for (int mt = 0; mt < MFR; mt++)
            #pragma unroll
            for (int h = 0; h < 2; h++) {
                const int row = m0 + wm + mt * 16 + lg + h * 8;
                float best = INFINITY; int bi = 0;
                #pragma unroll
                for (int nt = 0; nt < 4; nt++)
                    #pragma unroll
                    for (int e = 0; e < 2; e++) {
                        const int col = n0 + wn + nt * 8 + 2 * lt + e;
                        float s = g_cnorm[col] - 2.0f * acc[mt][nt][h * 2 + e];
                        if (s < best) { best = s; bi = col; }
                    }
                #pragma unroll
                for (int msk = 1; msk <= 2; msk <<= 1) {
                    float ov = __shfl_xor_sync(0xffffffffu, best, msk);
                    int   oi = __shfl_xor_sync(0xffffffffu, bi,   msk);
                    if (ov < best || (ov == best && oi < bi)) { best = ov; bi = oi; }
                }
                if (lt == 0) {
                    g_pval[(size_t)row * 32 + blockIdx.x * 4 + (wn >> 5)] = best;
                    g_pidx[(size_t)row * 32 + blockIdx.x * 4 + (wn >> 5)] = bi;
                }
            }
    }
}

// ---------------- small kernels ----------------
__global__ void k_zero() {
    int t = threadIdx.x;
    if (t < NCODE) g_counts[t] = 0;
    if (t == 0)    g_loss_sum = 0.0f;
}

__global__ void k_cnorm(const float* __restrict__ cb) {
    int c = blockIdx.x * blockDim.x + threadIdx.x;
    if (c < NCODE) {
        float s = 0.0f;
        const float* row = cb + (size_t)c * CDDIM;
        #pragma unroll 8
        for (int k = 0; k < CDDIM; k++) { float v = row[k]; s += v * v; }
        g_cnorm[c] = s;
    }
}

__global__ __launch_bounds__(256) void k_final(const float* __restrict__ CB,
                                               float* __restrict__ out, int full) {
    const int warp = threadIdx.x >> 5, lane = threadIdx.x & 31;
    const int row = blockIdx.x * 8 + warp;

    float v = g_pval[(size_t)row * 32 + lane];
    int  ii = g_pidx[(size_t)row * 32 + lane];
    #pragma unroll
    for (int off = 16; off > 0; off >>= 1) {
        float ov = __shfl_down_sync(0xffffffffu, v, off);
        int   oi = __shfl_down_sync(0xffffffffu, ii, off);
        if (ov < v || (ov == v && oi < ii)) { v = ov; ii = oi; }
    }
    int idx = __shfl_sync(0xffffffffu, ii, 0);

    float ls = 0.0f;
    for (int j = lane; j < CDDIM; j += 32) {
        float c = CB[(size_t)idx * CDDIM + j];
        float l = g_latent[(size_t)row * CDDIM + j];
        out[OFF_Q + (size_t)row * CDDIM + j] = c;
        float d = c - l; ls += d * d;
    }
    #pragma unroll
    for (int off = 16; off > 0; off >>= 1)
        ls += __shfl_down_sync(0xffffffffu, ls, off);
    if (lane == 0) {
        atomicAdd(&g_loss_sum, ls);
        atomicAdd(&g_counts[idx], 1);
    }
    if (full) {
        float* enc = out + OFF_ENC + (size_t)row * NCODE;
        for (int j = lane; j < NCODE; j += 32) enc[j] = (j == idx) ? 1.0f : 0.0f;
        if (lane == 0) out[OFF_IDX + row] = (float)idx;
    }
}

__global__ void k_scalar(float* __restrict__ out) {
    __shared__ float sh[256];
    int t = threadIdx.x;
    float e = 0.0f;
    for (int c = t; c < NCODE; c += 256) {
        float p = (float)g_counts[c] * (1.0f / (float)NROWS);
        e += p * logf(p + 1e-10f);
    }
    sh[t] = e;
    __syncthreads();
    for (int s = 128; s > 0; s >>= 1) {
        if (t < s) sh[t] += sh[t + s];
        __syncthreads();
    }
    if (t == 0) {
        out[OFF_LOSS] = 0.25f * g_loss_sum / ((float)NROWS * (float)CDDIM);
        out[OFF_PERP] = expf(-sh[0]);
    }
}

// ---------------- launch ----------------
extern "C" void kernel_launch(void* const* d_in, const int* in_sizes, int n_in,
                              void* d_out, int out_size) {
    const float* states      = (const float*)d_in[0];
    const float* next_states = (const float*)d_in[1];
    const float* W_s         = (const float*)d_in[2];
    const float* b_s         = (const float*)d_in[3];
    const float* W_p         = (const float*)d_in[4];
    const float* b_p         = (const float*)d_in[5];
    const float* codebook    = (const float*)d_in[6];
    float* out = (float*)d_out;
    int full = (out_size >= OFF_ENC) ? 1 : 0;

    // smem: MODE0/2 -> 2 stages * (2*128*32 + 2*128*32) words = 131072 B
    //       MODE1   -> 2 stages * (2*64*32 + 2*128*32)  words =  98304 B
    cudaFuncSetAttribute(gemm_mma<0, 128, DDIM>,
                         cudaFuncAttributeMaxDynamicSharedMemorySize, 131072);
    cudaFuncSetAttribute(gemm_mma<1, 64, 2 * EDIM>,
                         cudaFuncAttributeMaxDynamicSharedMemorySize, 98304);
    cudaFuncSetAttribute(gemm_mma<2, 128, CDDIM>,
                         cudaFuncAttributeMaxDynamicSharedMemorySize, 131072);

    k_zero<<<1, 1024>>>();
    k_cnorm<<<4, 256>>>(codebook);

    // encoder: M=8192, N=2048, K=1024 (two inputs via grid.z)
    gemm_mma<0, 128, DDIM><<<dim3(EDIM / 128, NROWS / 128, 2), 256, 131072>>>(
        states, next_states, W_s, b_s);
    // policy head: M=8192 (64-row tiles), N=256, K=4096
    gemm_mma<1, 64, 2 * EDIM><<<dim3(CDDIM / 128, NROWS / 64, 1), 256, 98304>>>(
        nullptr, nullptr, W_p, b_p);
    // scores: M=8192, N=1024 codes, K=256
    gemm_mma<2, 128, CDDIM><<<dim3(NCODE / 128, NROWS / 128, 1), 256, 131072>>>(
        nullptr, nullptr, codebook, nullptr);

    k_final<<<NROWS / 8, 256>>>(codebook, out, full);
    if (full) k_scalar<<<1, 256>>>(out);
}

// round 5
// speedup vs baseline: 1.7639x; 1.6495x over previous
#include <cuda_runtime.h>
#include <math.h>
#include <stdint.h>

// ---------------- problem constants ----------------
#define NROWS 8192     // B*T
#define DDIM  1024
#define EDIM  2048
#define CDDIM 256
#define NCODE 1024

// output layout (fp32 concat in reference return order)
#define OFF_Q     0
#define OFF_LOSS  2097152
#define OFF_PERP  2097153
#define OFF_ENC   2097154
#define OFF_IDX   10485762

// ---------------- scratch ----------------
__device__ float g_H1[(size_t)NROWS * EDIM];
__device__ float g_H2[(size_t)NROWS * EDIM];
__device__ float g_latent[(size_t)NROWS * CDDIM];
__device__ float g_cnorm[NCODE];
__device__ float g_pval[(size_t)NROWS * 32];
__device__ int   g_pidx[(size_t)NROWS * 32];
__device__ int   g_counts[NCODE];
__device__ float g_loss_sum;

// ---------------- helpers ----------------
__device__ __forceinline__ uint32_t smem_u32(const void* p) {
    uint32_t a;
    asm("{ .reg .u64 t; cvta.to.shared.u64 t, %1; cvt.u32.u64 %0, t; }" : "=r"(a) : "l"(p));
    return a;
}

#define CP16(dst, src) \
    asm volatile("cp.async.cg.shared.global [%0], [%1], 16;" :: "r"(dst), "l"(src))
#define CP_COMMIT() asm volatile("cp.async.commit_group;" ::: "memory")
#define CP_WAIT2()  asm volatile("cp.async.wait_group 2;" ::: "memory")

// RZ split of fp32 word into tf32 hi + residual lo (hw truncates lo's extra bits)
__device__ __forceinline__ void split32(uint32_t u, uint32_t& h, uint32_t& l) {
    h = u & 0xffffe000u;
    l = __float_as_uint(__uint_as_float(u) - __uint_as_float(h));
}

// D += A*B, m16n8k8 tf32. A row-major frags, B col-major frags.
__device__ __forceinline__ void mma8(float* c, const uint32_t* a, const uint32_t* b) {
    asm volatile(
        "mma.sync.aligned.m16n8k8.row.col.f32.tf32.tf32.f32 "
        "{%0,%1,%2,%3}, {%4,%5,%6,%7}, {%8,%9}, {%0,%1,%2,%3};"
        : "+f"(c[0]), "+f"(c[1]), "+f"(c[2]), "+f"(c[3])
        : "r"(a[0]), "r"(a[1]), "r"(a[2]), "r"(a[3]), "r"(b[0]), "r"(b[1]));
}

__device__ __forceinline__ float gelu_tanh(float x) {
    float x3 = x * x * x;
    float t  = tanhf(0.7978845608028654f * (x + 0.044715f * x3));
    return 0.5f * x * (1.0f + t);
}

// ---------------- main GEMM kernel ----------------
// MODE 0: H = gelu(A @ W_s + b_s)   (A = states or next_states by blockIdx.z)
// MODE 1: latent = [H1|H2] @ W_p + b_p
// MODE 2: scores = latent . codebook^T  -> per-warp partial argmin
// CTA tile 64 x 128, K-chunk 32, 8 warps (2m x 4n), warp tile 32 x 32.
// 4-stage cp.async pipeline; raw fp32 in smem; tf32 hi/lo split at frag load.
#define M_CTA 64
#define NSTG  4
#define ASZ   (M_CTA * 32)      // words per A stage
#define BSZ   (128 * 32)        // words per B stage
#define STG_W (ASZ + BSZ)       // 6144 words = 24KB
#define SMEM_BYTES (NSTG * STG_W * 4)   // 96KB

template <int MODE, int KTOT>
__global__ void __launch_bounds__(256, 2) gemm_mma(
    const float* __restrict__ A0, const float* __restrict__ A1,
    const float* __restrict__ Bsrc, const float* __restrict__ bias)
{
    extern __shared__ uint32_t smu[];
    constexpr int NCH = KTOT / 32;
    constexpr int MFR = 2;                 // two 16-row m-frags per warp

    const int tid  = threadIdx.x;
    const int wid  = tid >> 5, lane = tid & 31;
    const int wm   = (wid & 1) * 32;
    const int wn   = (wid >> 1) * 32;
    const int lt   = lane & 3, lg = lane >> 2;

    const int m0 = blockIdx.y * M_CTA, n0 = blockIdx.x * 128;
    const uint32_t sb = smem_u32(smu);

    float acc[MFR][4][4];
    #pragma unroll
    for (int i = 0; i < MFR; i++)
        #pragma unroll
        for (int j = 0; j < 4; j++)
            #pragma unroll
            for (int e = 0; e < 4; e++) acc[i][j][e] = 0.0f;

    auto copy_chunk = [&](int c, int stg) {
        const int k0 = c * 32;
        const uint32_t dA = sb + stg * STG_W * 4;
        const uint32_t dB = dA + ASZ * 4;
        // A: 64 rows x 8 16B-chunks = 512 -> 2/thread
        #pragma unroll
        for (int j = 0; j < 2; j++) {
            int q = tid + j * 256;
            int m = q >> 3, ch = q & 7;
            const float* src;
            if (MODE == 0)
                src = (blockIdx.z ? A1 : A0) + (size_t)(m0 + m) * DDIM + k0 + ch * 4;
            else if (MODE == 1)
                src = (k0 < EDIM)
                    ? g_H1 + (size_t)(m0 + m) * EDIM + k0 + ch * 4
                    : g_H2 + (size_t)(m0 + m) * EDIM + (k0 - EDIM) + ch * 4;
            else
                src = g_latent + (size_t)(m0 + m) * CDDIM + k0 + ch * 4;
            uint32_t dst = dA + (m * 32 + ((ch ^ (m & 7)) << 2)) * 4;
            CP16(dst, src);
        }
        // B: 1024 16B-chunks -> 4/thread
        #pragma unroll
        for (int j = 0; j < 4; j++) {
            int q = tid + j * 256;
            if (MODE == 2) {
                // codebook [n][k] rows: layout like A ([n][32])
                int n = q >> 3, ch = q & 7;
                const float* src = Bsrc + (size_t)(n0 + n) * CDDIM + k0 + ch * 4;
                uint32_t dst = dB + (n * 32 + ((ch ^ (n & 7)) << 2)) * 4;
                CP16(dst, src);
            } else {
                // weights [k][n]: layout [k][128]
                int k = q >> 5, ch = q & 31;
                const int ldb = (MODE == 0) ? EDIM : CDDIM;
                const float* src = Bsrc + (size_t)(k0 + k) * ldb + n0 + ch * 4;
                uint32_t dst = dB + (k * 128 + ((ch ^ ((k & 3) << 1)) << 2)) * 4;
                CP16(dst, src);
            }
        }
    };

    auto compute = [&](int stg) {
        const uint32_t* As = smu + stg * STG_W;
        const uint32_t* Bs = As + ASZ;
        #pragma unroll
        for (int s = 0; s < 4; s++) {
            uint32_t ah[MFR][4], al[MFR][4], bh[4][2], bl[4][2];
            // A fragments: (m, k=s*8+lt / +4)
            #pragma unroll
            for (int mt = 0; mt < MFR; mt++) {
                const int m = wm + mt * 16 + lg;
                const uint32_t* r0 = As + m * 32;
                const uint32_t* r1 = r0 + 8 * 32;
                const int c0 = (((2 * s)     ^ (m & 7)) << 2) + lt;
                const int c1 = (((2 * s + 1) ^ (m & 7)) << 2) + lt;
                split32(r0[c0], ah[mt][0], al[mt][0]);
                split32(r1[c0], ah[mt][1], al[mt][1]);
                split32(r0[c1], ah[mt][2], al[mt][2]);
                split32(r1[c1], ah[mt][3], al[mt][3]);
            }
            // B fragments: (k=s*8+lt / +4, n)
            if (MODE == 2) {
                #pragma unroll
                for (int nt = 0; nt < 4; nt++) {
                    const int n = wn + nt * 8 + lg;
                    const uint32_t* r = Bs + n * 32;
                    const int c0 = (((2 * s)     ^ (n & 7)) << 2) + lt;
                    const int c1 = (((2 * s + 1) ^ (n & 7)) << 2) + lt;
                    split32(r[c0], bh[nt][0], bl[nt][0]);
                    split32(r[c1], bh[nt][1], bl[nt][1]);
                }
            } else {
                const int k = s * 8 + lt;
                const uint32_t* r0 = Bs + k * 128;
                const uint32_t* r1 = r0 + 4 * 128;
                #pragma unroll
                for (int nt = 0; nt < 4; nt++) {
                    const int n = wn + nt * 8 + lg;
                    const int cc = (((n >> 2) ^ ((k & 3) << 1)) << 2) + (n & 3);
                    split32(r0[cc], bh[nt][0], bl[nt][0]);
                    split32(r1[cc], bh[nt][1], bl[nt][1]);
                }
            }
            #pragma unroll
            for (int mt = 0; mt < MFR; mt++)
                #pragma unroll
                for (int nt = 0; nt < 4; nt++) {
                    mma8(acc[mt][nt], ah[mt], bh[nt]);   // hi*hi
                    mma8(acc[mt][nt], ah[mt], bl[nt]);   // hi*lo
                    mma8(acc[mt][nt], al[mt], bh[nt]);   // lo*hi
                }
        }
    };

    // ---- prologue ----
    #pragma unroll
    for (int c = 0; c < NSTG - 1 && c < NCH; c++) { copy_chunk(c, c); CP_COMMIT(); }

    // ---- mainloop ----
    for (int c = 0; c < NCH; c++) {
        CP_WAIT2();
        __syncthreads();
        const int cn = c + NSTG - 1;
        if (cn < NCH) copy_chunk(cn, cn & (NSTG - 1));
        CP_COMMIT();
        compute(c & (NSTG - 1));
    }

    // ---- epilogue ----
    if (MODE == 0) {
        float* C = blockIdx.z ? g_H2 : g_H1;
        #pragma unroll
        for (int mt = 0; mt < MFR; mt++)
            #pragma unroll
            for (int h = 0; h < 2; h++) {
                const int row = m0 + wm + mt * 16 + lg + h * 8;
                float* cr = C + (size_t)row * EDIM + n0;
                #pragma unroll
                for (int nt = 0; nt < 4; nt++) {
                    const int col = wn + nt * 8 + 2 * lt;
                    float2 o;
                    o.x = gelu_tanh(acc[mt][nt][h * 2 + 0] + bias[n0 + col]);
                    o.y = gelu_tanh(acc[mt][nt][h * 2 + 1] + bias[n0 + col + 1]);
                    *(float2*)(cr + col) = o;
                }
            }
    } else if (MODE == 1) {
        #pragma unroll
        for (int mt = 0; mt < MFR; mt++)
            #pragma unroll
            for (int h = 0; h < 2; h++) {
                const int row = m0 + wm + mt * 16 + lg + h * 8;
                float* cr = g_latent + (size_t)row * CDDIM + n0;
                #pragma unroll
                for (int nt = 0; nt < 4; nt++) {
                    const int col = wn + nt * 8 + 2 * lt;
                    float2 o;
                    o.x = acc[mt][nt][h * 2 + 0] + bias[n0 + col];
                    o.y = acc[mt][nt][h * 2 + 1] + bias[n0 + col + 1];
                    *(float2*)(cr + col) = o;
                }
            }
    } else {
        #pragma unroll
        for (int mt = 0; mt < MFR; mt++)
            #pragma unroll
            for (int h = 0; h < 2; h++) {
                const int row = m0 + wm + mt * 16 + lg + h * 8;
                float best = INFINITY; int bi = 0;
                #pragma unroll
                for (int nt = 0; nt < 4; nt++)
                    #pragma unroll
                    for (int e = 0; e < 2; e++) {
                        const int col = n0 + wn + nt * 8 + 2 * lt + e;
                        float s = g_cnorm[col] - 2.0f * acc[mt][nt][h * 2 + e];
                        if (s < best) { best = s; bi = col; }
                    }
                #pragma unroll
                for (int msk = 1; msk <= 2; msk <<= 1) {
                    float ov = __shfl_xor_sync(0xffffffffu, best, msk);
                    int   oi = __shfl_xor_sync(0xffffffffu, bi,   msk);
                    if (ov < best || (ov == best && oi < bi)) { best = ov; bi = oi; }
                }
                if (lt == 0) {
                    g_pval[(size_t)row * 32 + blockIdx.x * 4 + (wn >> 5)] = best;
                    g_pidx[(size_t)row * 32 + blockIdx.x * 4 + (wn >> 5)] = bi;
                }
            }
    }
}

// ---------------- small kernels ----------------
__global__ void k_zero() {
    int t = threadIdx.x;
    if (t < NCODE) g_counts[t] = 0;
    if (t == 0)    g_loss_sum = 0.0f;
}

__global__ void k_cnorm(const float* __restrict__ cb) {
    int c = blockIdx.x * blockDim.x + threadIdx.x;
    if (c < NCODE) {
        float s = 0.0f;
        const float* row = cb + (size_t)c * CDDIM;
        #pragma unroll 8
        for (int k = 0; k < CDDIM; k++) { float v = row[k]; s += v * v; }
        g_cnorm[c] = s;
    }
}

__global__ __launch_bounds__(256) void k_final(const float* __restrict__ CB,
                                               float* __restrict__ out, int full) {
    const int warp = threadIdx.x >> 5, lane = threadIdx.x & 31;
    const int row = blockIdx.x * 8 + warp;

    float v = g_pval[(size_t)row * 32 + lane];
    int  ii = g_pidx[(size_t)row * 32 + lane];
    #pragma unroll
    for (int off = 16; off > 0; off >>= 1) {
        float ov = __shfl_down_sync(0xffffffffu, v, off);
        int   oi = __shfl_down_sync(0xffffffffu, ii, off);
        if (ov < v || (ov == v && oi < ii)) { v = ov; ii = oi; }
    }
    int idx = __shfl_sync(0xffffffffu, ii, 0);

    float ls = 0.0f;
    for (int j = lane; j < CDDIM; j += 32) {
        float c = CB[(size_t)idx * CDDIM + j];
        float l = g_latent[(size_t)row * CDDIM + j];
        out[OFF_Q + (size_t)row * CDDIM + j] = c;
        float d = c - l; ls += d * d;
    }
    #pragma unroll
    for (int off = 16; off > 0; off >>= 1)
        ls += __shfl_down_sync(0xffffffffu, ls, off);
    if (lane == 0) {
        atomicAdd(&g_loss_sum, ls);
        atomicAdd(&g_counts[idx], 1);
    }
    if (full) {
        float* enc = out + OFF_ENC + (size_t)row * NCODE;
        for (int j = lane; j < NCODE; j += 32) enc[j] = (j == idx) ? 1.0f : 0.0f;
        if (lane == 0) out[OFF_IDX + row] = (float)idx;
    }
}

__global__ void k_scalar(float* __restrict__ out) {
    __shared__ float sh[256];
    int t = threadIdx.x;
    float e = 0.0f;
    for (int c = t; c < NCODE; c += 256) {
        float p = (float)g_counts[c] * (1.0f / (float)NROWS);
        e += p * logf(p + 1e-10f);
    }
    sh[t] = e;
    __syncthreads();
    for (int s = 128; s > 0; s >>= 1) {
        if (t < s) sh[t] += sh[t + s];
        __syncthreads();
    }
    if (t == 0) {
        out[OFF_LOSS] = 0.25f * g_loss_sum / ((float)NROWS * (float)CDDIM);
        out[OFF_PERP] = expf(-sh[0]);
    }
}

// ---------------- launch ----------------
extern "C" void kernel_launch(void* const* d_in, const int* in_sizes, int n_in,
                              void* d_out, int out_size) {
    const float* states      = (const float*)d_in[0];
    const float* next_states = (const float*)d_in[1];
    const float* W_s         = (const float*)d_in[2];
    const float* b_s         = (const float*)d_in[3];
    const float* W_p         = (const float*)d_in[4];
    const float* b_p         = (const float*)d_in[5];
    const float* codebook    = (const float*)d_in[6];
    float* out = (float*)d_out;
    int full = (out_size >= OFF_ENC) ? 1 : 0;

    cudaFuncSetAttribute(gemm_mma<0, DDIM>,
                         cudaFuncAttributeMaxDynamicSharedMemorySize, SMEM_BYTES);
    cudaFuncSetAttribute(gemm_mma<1, 2 * EDIM>,
                         cudaFuncAttributeMaxDynamicSharedMemorySize, SMEM_BYTES);
    cudaFuncSetAttribute(gemm_mma<2, CDDIM>,
                         cudaFuncAttributeMaxDynamicSharedMemorySize, SMEM_BYTES);

    k_zero<<<1, 1024>>>();
    k_cnorm<<<4, 256>>>(codebook);

    // encoder: M=8192, N=2048, K=1024 (two inputs via grid.z)
    gemm_mma<0, DDIM><<<dim3(EDIM / 128, NROWS / M_CTA, 2), 256, SMEM_BYTES>>>(
        states, next_states, W_s, b_s);
    // policy head: M=8192, N=256, K=4096
    gemm_mma<1, 2 * EDIM><<<dim3(CDDIM / 128, NROWS / M_CTA, 1), 256, SMEM_BYTES>>>(
        nullptr, nullptr, W_p, b_p);
    // scores: M=8192, N=1024 codes, K=256
    gemm_mma<2, CDDIM><<<dim3(NCODE / 128, NROWS / M_CTA, 1), 256, SMEM_BYTES>>>(
        nullptr, nullptr, codebook, nullptr);

    k_final<<<NROWS / 8, 256>>>(codebook, out, full);
    if (full) k_scalar<<<1, 256>>>(out);
}

// round 6
// speedup vs baseline: 1.7660x; 1.0012x over previous
#include <cuda_runtime.h>
#include <math.h>
#include <stdint.h>

// ---------------- problem constants ----------------
#define NROWS 8192     // B*T
#define DDIM  1024
#define EDIM  2048
#define CDDIM 256
#define NCODE 1024

// output layout (fp32 concat in reference return order)
#define OFF_Q     0
#define OFF_LOSS  2097152
#define OFF_PERP  2097153
#define OFF_ENC   2097154
#define OFF_IDX   10485762

// ---------------- scratch ----------------
__device__ float g_H1[(size_t)NROWS * EDIM];
__device__ float g_H2[(size_t)NROWS * EDIM];
__device__ float g_latent[(size_t)NROWS * CDDIM];
__device__ float g_cnorm[NCODE];
__device__ float g_pval[(size_t)NROWS * 16];
__device__ int   g_pidx[(size_t)NROWS * 16];
__device__ int   g_counts[NCODE];
__device__ float g_loss_sum;

// ---------------- helpers ----------------
__device__ __forceinline__ uint32_t smem_u32(const void* p) {
    uint32_t a;
    asm("{ .reg .u64 t; cvta.to.shared.u64 t, %1; cvt.u32.u64 %0, t; }" : "=r"(a) : "l"(p));
    return a;
}

#define CP16(dst, src) \
    asm volatile("cp.async.cg.shared.global [%0], [%1], 16;" :: "r"(dst), "l"(src))
#define CP_COMMIT() asm volatile("cp.async.commit_group;" ::: "memory")

template <int N>
__device__ __forceinline__ void cp_wait() {
    asm volatile("cp.async.wait_group %0;" :: "n"(N) : "memory");
}

// RZ split of fp32 word into tf32 hi + residual lo
__device__ __forceinline__ void split32(uint32_t u, uint32_t& h, uint32_t& l) {
    h = u & 0xffffe000u;
    l = __float_as_uint(__uint_as_float(u) - __uint_as_float(h));
}

// D += A*B, m16n8k8 tf32. A row-major frags, B col-major frags.
__device__ __forceinline__ void mma8(float* c, const uint32_t* a, const uint32_t* b) {
    asm volatile(
        "mma.sync.aligned.m16n8k8.row.col.f32.tf32.tf32.f32 "
        "{%0,%1,%2,%3}, {%4,%5,%6,%7}, {%8,%9}, {%0,%1,%2,%3};"
        : "+f"(c[0]), "+f"(c[1]), "+f"(c[2]), "+f"(c[3])
        : "r"(a[0]), "r"(a[1]), "r"(a[2]), "r"(a[3]), "r"(b[0]), "r"(b[1]));
}

__device__ __forceinline__ float gelu_tanh(float x) {
    float x3 = x * x * x;
    float t  = tanhf(0.7978845608028654f * (x + 0.044715f * x3));
    return 0.5f * x * (1.0f + t);
}

// ---------------- main GEMM kernel ----------------
// MODE 0: H = gelu(A @ W_s + b_s)    CTA 64x256, warp 32x64, NSTG=2
// MODE 1: latent = [H1|H2] @ W_p+b_p CTA 64x128, warp 32x32, NSTG=4
// MODE 2: scores -> partial argmin   CTA 64x256, warp 32x64, NSTG=2
template <int MODE, int KTOT>
__global__ void __launch_bounds__(256, 2) gemm_mma(
    const float* __restrict__ A0, const float* __restrict__ A1,
    const float* __restrict__ Bsrc, const float* __restrict__ bias)
{
    extern __shared__ uint32_t smu[];
    constexpr int NCTA = (MODE == 1) ? 128 : 256;
    constexpr int WN   = (MODE == 1) ? 32 : 64;
    constexpr int NNT  = WN / 8;
    constexpr int NSTG = (MODE == 1) ? 4 : 2;
    constexpr int ASZ  = 64 * 32;
    constexpr int BSZ  = NCTA * 32;
    constexpr int STG_W = ASZ + BSZ;
    constexpr int NCH  = KTOT / 32;
    constexpr int MFR  = 2;

    const int tid  = threadIdx.x;
    const int wid  = tid >> 5, lane = tid & 31;
    const int wm   = (wid & 1) * 32;
    const int wn   = (wid >> 1) * WN;
    const int lt   = lane & 3, lg = lane >> 2;

    const int m0 = blockIdx.y * 64, n0 = blockIdx.x * NCTA;
    const uint32_t sb = smem_u32(smu);

    float acc[MFR][NNT][4];
    #pragma unroll
    for (int i = 0; i < MFR; i++)
        #pragma unroll
        for (int j = 0; j < NNT; j++)
            #pragma unroll
            for (int e = 0; e < 4; e++) acc[i][j][e] = 0.0f;

    auto copy_chunk = [&](int c, int stg) {
        const int k0 = c * 32;
        const uint32_t dA = sb + stg * STG_W * 4;
        const uint32_t dB = dA + ASZ * 4;
        // A: 64 rows x 8 chunks = 512 -> 2/thread
        #pragma unroll
        for (int j = 0; j < 2; j++) {
            int q = tid + j * 256;
            int m = q >> 3, ch = q & 7;
            const float* src;
            if (MODE == 0)
                src = (blockIdx.z ? A1 : A0) + (size_t)(m0 + m) * DDIM + k0 + ch * 4;
            else if (MODE == 1)
                src = (k0 < EDIM)
                    ? g_H1 + (size_t)(m0 + m) * EDIM + k0 + ch * 4
                    : g_H2 + (size_t)(m0 + m) * EDIM + (k0 - EDIM) + ch * 4;
            else
                src = g_latent + (size_t)(m0 + m) * CDDIM + k0 + ch * 4;
            uint32_t dst = dA + (m * 32 + ((ch ^ (m & 7)) << 2)) * 4;
            CP16(dst, src);
        }
        // B
        if (MODE == 2) {
            // codebook [n][k] rows: 256 rows x 8 chunks = 2048 -> 8/thread
            #pragma unroll
            for (int j = 0; j < 8; j++) {
                int q = tid + j * 256;
                int n = q >> 3, ch = q & 7;
                const float* src = Bsrc + (size_t)(n0 + n) * CDDIM + k0 + ch * 4;
                uint32_t dst = dB + (n * 32 + ((ch ^ (n & 7)) << 2)) * 4;
                CP16(dst, src);
            }
        } else {
            // weights [k][n]: 32 rows x NCTA/4 chunks
            constexpr int CPR = NCTA / 4;              // chunks per row
            constexpr int NJ  = 32 * CPR / 256;        // per-thread
            const int ldb = (MODE == 0) ? EDIM : CDDIM;
            #pragma unroll
            for (int j = 0; j < NJ; j++) {
                int q = tid + j * 256;
                int k = q / CPR, ch = q % CPR;
                const float* src = Bsrc + (size_t)(k0 + k) * ldb + n0 + ch * 4;
                uint32_t dst = dB + (k * NCTA + ((ch ^ ((k & 3) << 1)) << 2)) * 4;
                CP16(dst, src);
            }
        }
    };

    auto compute = [&](int stg) {
        const uint32_t* As = smu + stg * STG_W;
        const uint32_t* Bs = As + ASZ;
        #pragma unroll
        for (int s = 0; s < 4; s++) {
            uint32_t ah[MFR][4], al[MFR][4];
            #pragma unroll
            for (int mt = 0; mt < MFR; mt++) {
                const int m = wm + mt * 16 + lg;
                const uint32_t* r0 = As + m * 32;
                const uint32_t* r1 = r0 + 8 * 32;
                const int c0 = (((2 * s)     ^ (m & 7)) << 2) + lt;
                const int c1 = (((2 * s + 1) ^ (m & 7)) << 2) + lt;
                split32(r0[c0], ah[mt][0], al[mt][0]);
                split32(r1[c0], ah[mt][1], al[mt][1]);
                split32(r0[c1], ah[mt][2], al[mt][2]);
                split32(r1[c1], ah[mt][3], al[mt][3]);
            }
            #pragma unroll
            for (int nt = 0; nt < NNT; nt++) {
                uint32_t bh[2], bl[2];
                if (MODE == 2) {
                    const int n = wn + nt * 8 + lg;
                    const uint32_t* r = Bs + n * 32;
                    const int c0 = (((2 * s)     ^ (n & 7)) << 2) + lt;
                    const int c1 = (((2 * s + 1) ^ (n & 7)) << 2) + lt;
                    split32(r[c0], bh[0], bl[0]);
                    split32(r[c1], bh[1], bl[1]);
                } else {
                    const int k = s * 8 + lt;
                    const uint32_t* r0 = Bs + k * NCTA;
                    const uint32_t* r1 = r0 + 4 * NCTA;
                    const int n = wn + nt * 8 + lg;
                    const int cc = (((n >> 2) ^ ((k & 3) << 1)) << 2) + (n & 3);
                    split32(r0[cc], bh[0], bl[0]);
                    split32(r1[cc], bh[1], bl[1]);
                }
                #pragma unroll
                for (int mt = 0; mt < MFR; mt++) {
                    mma8(acc[mt][nt], ah[mt], bh);   // hi*hi
                    mma8(acc[mt][nt], ah[mt], bl);   // hi*lo
                    mma8(acc[mt][nt], al[mt], bh);   // lo*hi
                }
            }
        }
    };

    // ---- prologue ----
    #pragma unroll
    for (int c = 0; c < NSTG - 1 && c < NCH; c++) { copy_chunk(c, c); CP_COMMIT(); }

    // ---- mainloop ----
    for (int c = 0; c < NCH; c++) {
        cp_wait<NSTG - 2>();
        __syncthreads();
        const int cn = c + NSTG - 1;
        if (cn < NCH) copy_chunk(cn, cn & (NSTG - 1));
        CP_COMMIT();
        compute(c & (NSTG - 1));
    }

    // ---- epilogue ----
    if (MODE == 0) {
        float* C = blockIdx.z ? g_H2 : g_H1;
        #pragma unroll
        for (int mt = 0; mt < MFR; mt++)
            #pragma unroll
            for (int h = 0; h < 2; h++) {
                const int row = m0 + wm + mt * 16 + lg + h * 8;
                float* cr = C + (size_t)row * EDIM + n0;
                #pragma unroll
                for (int nt = 0; nt < NNT; nt++) {
                    const int col = wn + nt * 8 + 2 * lt;
                    float2 o;
                    o.x = gelu_tanh(acc[mt][nt][h * 2 + 0] + bias[n0 + col]);
                    o.y = gelu_tanh(acc[mt][nt][h * 2 + 1] + bias[n0 + col + 1]);
                    *(float2*)(cr + col) = o;
                }
            }
    } else if (MODE == 1) {
        #pragma unroll
        for (int mt = 0; mt < MFR; mt++)
            #pragma unroll
            for (int h = 0; h < 2; h++) {
                const int row = m0 + wm + mt * 16 + lg + h * 8;
                float* cr = g_latent + (size_t)row * CDDIM + n0;
                #pragma unroll
                for (int nt = 0; nt < NNT; nt++) {
                    const int col = wn + nt * 8 + 2 * lt;
                    float2 o;
                    o.x = acc[mt][nt][h * 2 + 0] + bias[n0 + col];
                    o.y = acc[mt][nt][h * 2 + 1] + bias[n0 + col + 1];
                    *(float2*)(cr + col) = o;
                }
            }
    } else {
        // per-warp partial argmin over its 64 codes
        #pragma unroll
        for (int mt = 0; mt < MFR; mt++)
            #pragma unroll
            for (int h = 0; h < 2; h++) {
                const int row = m0 + wm + mt * 16 + lg + h * 8;
                float best = INFINITY; int bi = 0;
                #pragma unroll
                for (int nt = 0; nt < NNT; nt++)
                    #pragma unroll
                    for (int e = 0; e < 2; e++) {
                        const int col = n0 + wn + nt * 8 + 2 * lt + e;
                        float s = g_cnorm[col] - 2.0f * acc[mt][nt][h * 2 + e];
                        if (s < best) { best = s; bi = col; }
                    }
                #pragma unroll
                for (int msk = 1; msk <= 2; msk <<= 1) {
                    float ov = __shfl_xor_sync(0xffffffffu, best, msk);
                    int   oi = __shfl_xor_sync(0xffffffffu, bi,   msk);
                    if (ov < best || (ov == best && oi < bi)) { best = ov; bi = oi; }
                }
                if (lt == 0) {
                    // 16 slots/row: blockIdx.x (0..3) * 4 + warp-n (0..3)
                    g_pval[(size_t)row * 16 + blockIdx.x * 4 + (wid >> 1)] = best;
                    g_pidx[(size_t)row * 16 + blockIdx.x * 4 + (wid >> 1)] = bi;
                }
            }
    }
}

// ---------------- small kernels ----------------
__global__ void k_zero() {
    int t = threadIdx.x;
    if (t < NCODE) g_counts[t] = 0;
    if (t == 0)    g_loss_sum = 0.0f;
}

__global__ void k_cnorm(const float* __restrict__ cb) {
    int c = blockIdx.x * blockDim.x + threadIdx.x;
    if (c < NCODE) {
        float s = 0.0f;
        const float* row = cb + (size_t)c * CDDIM;
        #pragma unroll 8
        for (int k = 0; k < CDDIM; k++) { float v = row[k]; s += v * v; }
        g_cnorm[c] = s;
    }
}

__global__ __launch_bounds__(256) void k_final(const float* __restrict__ CB,
                                               float* __restrict__ out, int full) {
    const int warp = threadIdx.x >> 5, lane = threadIdx.x & 31;
    const int row = blockIdx.x * 8 + warp;

    float v = INFINITY; int ii = 0x7fffffff;
    if (lane < 16) { v = g_pval[(size_t)row * 16 + lane]; ii = g_pidx[(size_t)row * 16 + lane]; }
    #pragma unroll
    for (int off = 16; off > 0; off >>= 1) {
        float ov = __shfl_down_sync(0xffffffffu, v, off);
        int   oi = __shfl_down_sync(0xffffffffu, ii, off);
        if (ov < v || (ov == v && oi < ii)) { v = ov; ii = oi; }
    }
    int idx = __shfl_sync(0xffffffffu, ii, 0);

    float ls = 0.0f;
    for (int j = lane; j < CDDIM; j += 32) {
        float c = CB[(size_t)idx * CDDIM + j];
        float l = g_latent[(size_t)row * CDDIM + j];
        out[OFF_Q + (size_t)row * CDDIM + j] = c;
        float d = c - l; ls += d * d;
    }
    #pragma unroll
    for (int off = 16; off > 0; off >>= 1)
        ls += __shfl_down_sync(0xffffffffu, ls, off);
    if (lane == 0) {
        atomicAdd(&g_loss_sum, ls);
        atomicAdd(&g_counts[idx], 1);
    }
    if (full) {
        float* enc = out + OFF_ENC + (size_t)row * NCODE;
        for (int j = lane; j < NCODE; j += 32) enc[j] = (j == idx) ? 1.0f : 0.0f;
        if (lane == 0) out[OFF_IDX + row] = (float)idx;
    }
}

__global__ void k_scalar(float* __restrict__ out) {
    __shared__ float sh[256];
    int t = threadIdx.x;
    float e = 0.0f;
    for (int c = t; c < NCODE; c += 256) {
        float p = (float)g_counts[c] * (1.0f / (float)NROWS);
        e += p * logf(p + 1e-10f);
    }
    sh[t] = e;
    __syncthreads();
    for (int s = 128; s > 0; s >>= 1) {
        if (t < s) sh[t] += sh[t + s];
        __syncthreads();
    }
    if (t == 0) {
        out[OFF_LOSS] = 0.25f * g_loss_sum / ((float)NROWS * (float)CDDIM);
        out[OFF_PERP] = expf(-sh[0]);
    }
}

// ---------------- launch ----------------
extern "C" void kernel_launch(void* const* d_in, const int* in_sizes, int n_in,
                              void* d_out, int out_size) {
    const float* states      = (const float*)d_in[0];
    const float* next_states = (const float*)d_in[1];
    const float* W_s         = (const float*)d_in[2];
    const float* b_s         = (const float*)d_in[3];
    const float* W_p         = (const float*)d_in[4];
    const float* b_p         = (const float*)d_in[5];
    const float* codebook    = (const float*)d_in[6];
    float* out = (float*)d_out;
    int full = (out_size >= OFF_ENC) ? 1 : 0;

    // smem: MODE0/2: 2 stages * (64*32 + 256*32) words * 4 = 81920 B
    //       MODE1:   4 stages * (64*32 + 128*32) words * 4 = 98304 B
    constexpr int SM_W = 2 * (64 * 32 + 256 * 32) * 4;
    constexpr int SM_1 = 4 * (64 * 32 + 128 * 32) * 4;
    cudaFuncSetAttribute(gemm_mma<0, DDIM>,
                         cudaFuncAttributeMaxDynamicSharedMemorySize, SM_W);
    cudaFuncSetAttribute(gemm_mma<1, 2 * EDIM>,
                         cudaFuncAttributeMaxDynamicSharedMemorySize, SM_1);
    cudaFuncSetAttribute(gemm_mma<2, CDDIM>,
                         cudaFuncAttributeMaxDynamicSharedMemorySize, SM_W);

    k_zero<<<1, 1024>>>();
    k_cnorm<<<4, 256>>>(codebook);

    // encoder: M=8192, N=2048, K=1024 (two inputs via grid.z)
    gemm_mma<0, DDIM><<<dim3(EDIM / 256, NROWS / 64, 2), 256, SM_W>>>(
        states, next_states, W_s, b_s);
    // policy head: M=8192, N=256, K=4096
    gemm_mma<1, 2 * EDIM><<<dim3(CDDIM / 128, NROWS / 64, 1), 256, SM_1>>>(
        nullptr, nullptr, W_p, b_p);
    // scores: M=8192, N=1024 codes, K=256
    gemm_mma<2, CDDIM><<<dim3(NCODE / 256, NROWS / 64, 1), 256, SM_W>>>(
        nullptr, nullptr, codebook, nullptr);

    k_final<<<NROWS / 8, 256>>>(codebook, out, full);
    if (full) k_scalar<<<1, 256>>>(out);
}

// round 7
// speedup vs baseline: 2.5061x; 1.4191x over previous
#include <cuda_runtime.h>
#include <cuda_fp16.h>
#include <math.h>
#include <stdint.h>

// ---------------- problem constants ----------------
#define NROWS 8192     // B*T
#define DDIM  1024
#define EDIM  2048
#define CDDIM 256
#define NCODE 1024

// output layout (fp32 concat in reference return order)
#define OFF_Q     0
#define OFF_LOSS  2097152
#define OFF_PERP  2097153
#define OFF_ENC   2097154
#define OFF_IDX   10485762

// ---------------- scratch ----------------
// fp16 hi/lo pre-split operands (u32 = packed half2, k-contiguous)
__device__ uint32_t g_Sh[(size_t)2 * NROWS * (DDIM / 2)];      // states|next rows
__device__ uint32_t g_Sl[(size_t)2 * NROWS * (DDIM / 2)];
__device__ uint32_t g_Wsh[(size_t)EDIM * (DDIM / 2)];          // W_s^T  [E][D]
__device__ uint32_t g_Wsl[(size_t)EDIM * (DDIM / 2)];
__device__ uint32_t g_Wph[(size_t)CDDIM * (2 * EDIM / 2)];     // W_p^T  [CD][2E]
__device__ uint32_t g_Wpl[(size_t)CDDIM * (2 * EDIM / 2)];
__device__ uint32_t g_Hh[(size_t)NROWS * (2 * EDIM / 2)];      // H = gelu(...)  [M][4096]
__device__ uint32_t g_Hl[(size_t)NROWS * (2 * EDIM / 2)];

__device__ float g_latent[(size_t)NROWS * CDDIM];
__device__ float g_cnorm[NCODE];
__device__ float g_pval[(size_t)NROWS * 16];
__device__ int   g_pidx[(size_t)NROWS * 16];
__device__ int   g_counts[NCODE];
__device__ float g_loss_sum;

// ---------------- helpers ----------------
__device__ __forceinline__ uint32_t smem_u32(const void* p) {
    uint32_t a;
    asm("{ .reg .u64 t; cvta.to.shared.u64 t, %1; cvt.u32.u64 %0, t; }" : "=r"(a) : "l"(p));
    return a;
}

#define CP16(dst, src) \
    asm volatile("cp.async.cg.shared.global [%0], [%1], 16;" :: "r"(dst), "l"(src))
#define CP_COMMIT() asm volatile("cp.async.commit_group;" ::: "memory")
template <int N>
__device__ __forceinline__ void cp_wait() {
    asm volatile("cp.async.wait_group %0;" :: "n"(N) : "memory");
}

// fp16 hi/lo split of an fp32 value
__device__ __forceinline__ void split_h(float v, uint16_t& h, uint16_t& l) {
    __half hh = __float2half_rn(v);
    float r = v - __half2float(hh);
    h = __half_as_ushort(hh);
    l = __half_as_ushort(__float2half_rn(r));
}

// tf32 split (score kernel)
__device__ __forceinline__ void split32(uint32_t u, uint32_t& h, uint32_t& l) {
    h = u & 0xffffe000u;
    l = __float_as_uint(__uint_as_float(u) - __uint_as_float(h));
}

// fp16 mma: D += A*B, m16n8k16, fp32 accumulate
__device__ __forceinline__ void mma16(float* c, const uint32_t* a, const uint32_t* b) {
    asm volatile(
        "mma.sync.aligned.m16n8k16.row.col.f32.f16.f16.f32 "
        "{%0,%1,%2,%3}, {%4,%5,%6,%7}, {%8,%9}, {%0,%1,%2,%3};"
        : "+f"(c[0]), "+f"(c[1]), "+f"(c[2]), "+f"(c[3])
        : "r"(a[0]), "r"(a[1]), "r"(a[2]), "r"(a[3]), "r"(b[0]), "r"(b[1]));
}

// tf32 mma: m16n8k8
__device__ __forceinline__ void mma8(float* c, const uint32_t* a, const uint32_t* b) {
    asm volatile(
        "mma.sync.aligned.m16n8k8.row.col.f32.tf32.tf32.f32 "
        "{%0,%1,%2,%3}, {%4,%5,%6,%7}, {%8,%9}, {%0,%1,%2,%3};"
        : "+f"(c[0]), "+f"(c[1]), "+f"(c[2]), "+f"(c[3])
        : "r"(a[0]), "r"(a[1]), "r"(a[2]), "r"(a[3]), "r"(b[0]), "r"(b[1]));
}

__device__ __forceinline__ float gelu_tanh(float x) {
    float x3 = x * x * x;
    float t  = tanhf(0.7978845608028654f * (x + 0.044715f * x3));
    return 0.5f * x * (1.0f + t);
}

// ---------------- pre-split kernels ----------------
// row-major fp32 -> packed fp16 h/l (into g_Sh/g_Sl at u32 offset)
__global__ void k_split_rm(const float* __restrict__ src, uint32_t off, int npairs) {
    int i = blockIdx.x * blockDim.x + threadIdx.x;
    if (i >= npairs) return;
    float2 v = ((const float2*)src)[i];
    uint16_t h0, l0, h1, l1;
    split_h(v.x, h0, l0);
    split_h(v.y, h1, l1);
    g_Sh[off + i] = (uint32_t)h0 | ((uint32_t)h1 << 16);
    g_Sl[off + i] = (uint32_t)l0 | ((uint32_t)l1 << 16);
}

// transpose [K][N] fp32 -> [N][K] fp16 h/l  (which: 0 = W_s, 1 = W_p)
__global__ void k_split_tr(const float* __restrict__ src, int K, int N, int which) {
    __shared__ float ts[32][33];
    int tx = threadIdx.x, ty = threadIdx.y;
    int n0 = blockIdx.x * 32, k0 = blockIdx.y * 32;
    #pragma unroll
    for (int r = 0; r < 4; r++)
        ts[ty + 8 * r][tx] = src[(size_t)(k0 + ty + 8 * r) * N + n0 + tx];
    __syncthreads();
    __half* dh = (__half*)(which ? g_Wph : g_Wsh);
    __half* dl = (__half*)(which ? g_Wpl : g_Wsl);
    #pragma unroll
    for (int r = 0; r < 4; r++) {
        int n = n0 + ty + 8 * r, k = k0 + tx;
        float v = ts[tx][ty + 8 * r];
        uint16_t h, l;
        split_h(v, h, l);
        dh[(size_t)n * K + k] = __ushort_as_half(h);
        dl[(size_t)n * K + k] = __ushort_as_half(l);
    }
}

// ---------------- fp16 split GEMM ----------------
// MODE 0: H = gelu(S @ Ws^T + b_s) -> g_Hh/g_Hl   (z selects states/next, col half)
// MODE 1: latent = H @ Wp^T + b_p  -> g_latent (fp32)
// CTA 64x128, 8 warps (2m x 4n), warp 32x32, K-chunk 32 fp16, NSTG=4.
// smem per stage: A 64x32 u32-words (h 0..15, l 16..31), B 128x32 -> 24KB.
template <int MODE, int KT>
__global__ void __launch_bounds__(256, 2) gemm_f16(const float* __restrict__ bias) {
    extern __shared__ uint32_t smu[];
    constexpr int KW   = KT / 2;          // u32 words per row
    constexpr int NCH  = KT / 32;
    constexpr int ASZ  = 64 * 32;
    constexpr int BSZ  = 128 * 32;
    constexpr int STG  = ASZ + BSZ;
    constexpr int NSTG = 4;

    const uint32_t* Ah = (MODE == 0) ? g_Sh : g_Hh;
    const uint32_t* Al = (MODE == 0) ? g_Sl : g_Hl;
    const uint32_t* Bh = (MODE == 0) ? g_Wsh : g_Wph;
    const uint32_t* Bl = (MODE == 0) ? g_Wsl : g_Wpl;

    const int tid = threadIdx.x;
    const int wid = tid >> 5, lane = tid & 31;
    const int wm  = (wid & 1) * 32;
    const int wn  = (wid >> 1) * 32;
    const int lt  = lane & 3, lg = lane >> 2;

    const int m0 = blockIdx.y * 64, n0 = blockIdx.x * 128;
    const size_t arow0 = (MODE == 0) ? ((size_t)blockIdx.z * NROWS + m0) : (size_t)m0;
    const uint32_t sb = smem_u32(smu);

    float acc[2][4][4];
    #pragma unroll
    for (int i = 0; i < 2; i++)
        #pragma unroll
        for (int j = 0; j < 4; j++)
            #pragma unroll
            for (int e = 0; e < 4; e++) acc[i][j][e] = 0.0f;

    auto copy_chunk = [&](int c, int stg) {
        const uint32_t dA = sb + stg * STG * 4;
        const uint32_t dB = dA + ASZ * 4;
        // A: 64 rows x 8 parts (0-3 hi, 4-7 lo) = 512 units -> 2/thread
        #pragma unroll
        for (int j = 0; j < 2; j++) {
            int u = tid + j * 256;
            int m = u >> 3, p = u & 7;
            const uint32_t* s = ((p < 4) ? Ah : Al)
                + (arow0 + m) * KW + c * 16 + (p & 3) * 4;
            uint32_t dst = dA + (m * 32 + ((p ^ (m & 7)) << 2)) * 4;
            CP16(dst, s);
        }
        // B: 128 rows x 8 parts = 1024 units -> 4/thread
        #pragma unroll
        for (int j = 0; j < 4; j++) {
            int u = tid + j * 256;
            int n = u >> 3, p = u & 7;
            const uint32_t* s = ((p < 4) ? Bh : Bl)
                + (size_t)(n0 + n) * KW + c * 16 + (p & 3) * 4;
            uint32_t dst = dB + (n * 32 + ((p ^ (n & 7)) << 2)) * 4;
            CP16(dst, s);
        }
    };

    auto compute = [&](int stg) {
        const uint32_t* As = smu + stg * STG;
        const uint32_t* Bs = As + ASZ;
        #pragma unroll
        for (int s = 0; s < 2; s++) {      // two k16 slabs per chunk
            const int q0 = (((2 * s)     ^ lg) << 2) + lt;
            const int q1 = (((2 * s + 1) ^ lg) << 2) + lt;
            const int q2 = (((2 * s + 4) ^ lg) << 2) + lt;
            const int q3 = (((2 * s + 5) ^ lg) << 2) + lt;
            uint32_t ah[2][4], al[2][4];
            #pragma unroll
            for (int mt = 0; mt < 2; mt++) {
                const uint32_t* r0 = As + (wm + 16 * mt + lg) * 32;
                const uint32_t* r8 = r0 + 8 * 32;
                ah[mt][0] = r0[q0]; ah[mt][1] = r8[q0];
                ah[mt][2] = r0[q1]; ah[mt][3] = r8[q1];
                al[mt][0] = r0[q2]; al[mt][1] = r8[q2];
                al[mt][2] = r0[q3]; al[mt][3] = r8[q3];
            }
            #pragma unroll
            for (int nt = 0; nt < 4; nt++) {
                const uint32_t* rn = Bs + (wn + 8 * nt + lg) * 32;
                uint32_t bh[2] = {rn[q0], rn[q1]};
                uint32_t bl[2] = {rn[q2], rn[q3]};
                #pragma unroll
                for (int mt = 0; mt < 2; mt++) {
                    mma16(acc[mt][nt], ah[mt], bh);   // hi*hi
                    mma16(acc[mt][nt], ah[mt], bl);   // hi*lo
                    mma16(acc[mt][nt], al[mt], bh);   // lo*hi
                }
            }
        }
    };

    // ---- prologue ----
    #pragma unroll
    for (int c = 0; c < NSTG - 1 && c < NCH; c++) { copy_chunk(c, c); CP_COMMIT(); }

    // ---- mainloop ----
    for (int c = 0; c < NCH; c++) {
        cp_wait<NSTG - 2>();
        __syncthreads();
        const int cn = c + NSTG - 1;
        if (cn < NCH) copy_chunk(cn, cn & (NSTG - 1));
        CP_COMMIT();
        compute(c & (NSTG - 1));
    }

    // ---- epilogue ----
    if (MODE == 0) {
        const int zoff = blockIdx.z ? EDIM : 0;   // H col half
        #pragma unroll
        for (int mt = 0; mt < 2; mt++)
            #pragma unroll
            for (int h = 0; h < 2; h++) {
                const int row = m0 + wm + mt * 16 + lg + h * 8;
                #pragma unroll
                for (int nt = 0; nt < 4; nt++) {
                    const int col = wn + nt * 8 + 2 * lt;
                    float g0 = gelu_tanh(acc[mt][nt][h * 2 + 0] + bias[n0 + col]);
                    float g1 = gelu_tanh(acc[mt][nt][h * 2 + 1] + bias[n0 + col + 1]);
                    uint16_t h0, l0, h1, l1;
                    split_h(g0, h0, l0);
                    split_h(g1, h1, l1);
                    size_t cw = (size_t)row * (2 * EDIM / 2) + ((zoff + n0 + col) >> 1);
                    g_Hh[cw] = (uint32_t)h0 | ((uint32_t)h1 << 16);
                    g_Hl[cw] = (uint32_t)l0 | ((uint32_t)l1 << 16);
                }
            }
    } else {
        #pragma unroll
        for (int mt = 0; mt < 2; mt++)
            #pragma unroll
            for (int h = 0; h < 2; h++) {
                const int row = m0 + wm + mt * 16 + lg + h * 8;
                float* cr = g_latent + (size_t)row * CDDIM + n0;
                #pragma unroll
                for (int nt = 0; nt < 4; nt++) {
                    const int col = wn + nt * 8 + 2 * lt;
                    float2 o;
                    o.x = acc[mt][nt][h * 2 + 0] + bias[n0 + col];
                    o.y = acc[mt][nt][h * 2 + 1] + bias[n0 + col + 1];
                    *(float2*)(cr + col) = o;
                }
            }
    }
}

// ---------------- score GEMM (3x tf32, from R6) ----------------
// scores = latent . codebook^T -> per-warp partial argmin
// CTA 64x256, warp 32x64, NSTG=2
__global__ void __launch_bounds__(256, 2) gemm_score(const float* __restrict__ CB) {
    extern __shared__ uint32_t smu[];
    constexpr int NCTA = 256, NNT = 8, NSTG = 2;
    constexpr int ASZ = 64 * 32, BSZ = NCTA * 32, STG_W = ASZ + BSZ;
    constexpr int NCH = CDDIM / 32;

    const int tid = threadIdx.x;
    const int wid = tid >> 5, lane = tid & 31;
    const int wm  = (wid & 1) * 32;
    const int wn  = (wid >> 1) * 64;
    const int lt  = lane & 3, lg = lane >> 2;

    const int m0 = blockIdx.y * 64, n0 = blockIdx.x * NCTA;
    const uint32_t sb = smem_u32(smu);

    float acc[2][NNT][4];
    #pragma unroll
    for (int i = 0; i < 2; i++)
        #pragma unroll
        for (int j = 0; j < NNT; j++)
            #pragma unroll
            for (int e = 0; e < 4; e++) acc[i][j][e] = 0.0f;

    auto copy_chunk = [&](int c, int stg) {
        const int k0 = c * 32;
        const uint32_t dA = sb + stg * STG_W * 4;
        const uint32_t dB = dA + ASZ * 4;
        #pragma unroll
        for (int j = 0; j < 2; j++) {
            int q = tid + j * 256;
            int m = q >> 3, ch = q & 7;
            const float* src = g_latent + (size_t)(m0 + m) * CDDIM + k0 + ch * 4;
            uint32_t dst = dA + (m * 32 + ((ch ^ (m & 7)) << 2)) * 4;
            CP16(dst, src);
        }
        #pragma unroll
        for (int j = 0; j < 8; j++) {
            int q = tid + j * 256;
            int n = q >> 3, ch = q & 7;
            const float* src = CB + (size_t)(n0 + n) * CDDIM + k0 + ch * 4;
            uint32_t dst = dB + (n * 32 + ((ch ^ (n & 7)) << 2)) * 4;
            CP16(dst, src);
        }
    };

    auto compute = [&](int stg) {
        const uint32_t* As = smu + stg * STG_W;
        const uint32_t* Bs = As + ASZ;
        #pragma unroll
        for (int s = 0; s < 4; s++) {
            uint32_t ah[2][4], al[2][4];
            #pragma unroll
            for (int mt = 0; mt < 2; mt++) {
                const int m = wm + mt * 16 + lg;
                const uint32_t* r0 = As + m * 32;
                const uint32_t* r1 = r0 + 8 * 32;
                const int c0 = (((2 * s)     ^ (m & 7)) << 2) + lt;
                const int c1 = (((2 * s + 1) ^ (m & 7)) << 2) + lt;
                split32(r0[c0], ah[mt][0], al[mt][0]);
                split32(r1[c0], ah[mt][1], al[mt][1]);
                split32(r0[c1], ah[mt][2], al[mt][2]);
                split32(r1[c1], ah[mt][3], al[mt][3]);
            }
            #pragma unroll
            for (int nt = 0; nt < NNT; nt++) {
                const int n = wn + nt * 8 + lg;
                const uint32_t* r = Bs + n * 32;
                const int c0 = (((2 * s)     ^ (n & 7)) << 2) + lt;
                const int c1 = (((2 * s + 1) ^ (n & 7)) << 2) + lt;
                uint32_t bh[2], bl[2];
                split32(r[c0], bh[0], bl[0]);
                split32(r[c1], bh[1], bl[1]);
                #pragma unroll
                for (int mt = 0; mt < 2; mt++) {
                    mma8(acc[mt][nt], ah[mt], bh);
                    mma8(acc[mt][nt], ah[mt], bl);
                    mma8(acc[mt][nt], al[mt], bh);
                }
            }
        }
    };

    #pragma unroll
    for (int c = 0; c < NSTG - 1 && c < NCH; c++) { copy_chunk(c, c); CP_COMMIT(); }
    for (int c = 0; c < NCH; c++) {
        cp_wait<NSTG - 2>();
        __syncthreads();
        const int cn = c + NSTG - 1;
        if (cn < NCH) copy_chunk(cn, cn & (NSTG - 1));
        CP_COMMIT();
        compute(c & (NSTG - 1));
    }

    #pragma unroll
    for (int mt = 0; mt < 2; mt++)
        #pragma unroll
        for (int h = 0; h < 2; h++) {
            const int row = m0 + wm + mt * 16 + lg + h * 8;
            float best = INFINITY; int bi = 0;
            #pragma unroll
            for (int nt = 0; nt < NNT; nt++)
                #pragma unroll
                for (int e = 0; e < 2; e++) {
                    const int col = n0 + wn + nt * 8 + 2 * lt + e;
                    float s = g_cnorm[col] - 2.0f * acc[mt][nt][h * 2 + e];
                    if (s < best) { best = s; bi = col; }
                }
            #pragma unroll
            for (int msk = 1; msk <= 2; msk <<= 1) {
                float ov = __shfl_xor_sync(0xffffffffu, best, msk);
                int   oi = __shfl_xor_sync(0xffffffffu, bi,   msk);
                if (ov < best || (ov == best && oi < bi)) { best = ov; bi = oi; }
            }
            if (lt == 0) {
                g_pval[(size_t)row * 16 + blockIdx.x * 4 + (wid >> 1)] = best;
                g_pidx[(size_t)row * 16 + blockIdx.x * 4 + (wid >> 1)] = bi;
            }
        }
}

// ---------------- small kernels ----------------
__global__ void k_zero() {
    int t = threadIdx.x;
    if (t < NCODE) g_counts[t] = 0;
    if (t == 0)    g_loss_sum = 0.0f;
}

__global__ void k_cnorm(const float* __restrict__ cb) {
    int c = blockIdx.x * blockDim.x + threadIdx.x;
    if (c < NCODE) {
        float s = 0.0f;
        const float* row = cb + (size_t)c * CDDIM;
        #pragma unroll 8
        for (int k = 0; k < CDDIM; k++) { float v = row[k]; s += v * v; }
        g_cnorm[c] = s;
    }
}

__global__ __launch_bounds__(256) void k_final(const float* __restrict__ CB,
                                               float* __restrict__ out, int full) {
    const int warp = threadIdx.x >> 5, lane = threadIdx.x & 31;
    const int row = blockIdx.x * 8 + warp;

    float v = INFINITY; int ii = 0x7fffffff;
    if (lane < 16) { v = g_pval[(size_t)row * 16 + lane]; ii = g_pidx[(size_t)row * 16 + lane]; }
    #pragma unroll
    for (int off = 16; off > 0; off >>= 1) {
        float ov = __shfl_down_sync(0xffffffffu, v, off);
        int   oi = __shfl_down_sync(0xffffffffu, ii, off);
        if (ov < v || (ov == v && oi < ii)) { v = ov; ii = oi; }
    }
    int idx = __shfl_sync(0xffffffffu, ii, 0);

    float ls = 0.0f;
    for (int j = lane; j < CDDIM; j += 32) {
        float c = CB[(size_t)idx * CDDIM + j];
        float l = g_latent[(size_t)row * CDDIM + j];
        out[OFF_Q + (size_t)row * CDDIM + j] = c;
        float d = c - l; ls += d * d;
    }
    #pragma unroll
    for (int off = 16; off > 0; off >>= 1)
        ls += __shfl_down_sync(0xffffffffu, ls, off);
    if (lane == 0) {
        atomicAdd(&g_loss_sum, ls);
        atomicAdd(&g_counts[idx], 1);
    }
    if (full) {
        float* enc = out + OFF_ENC + (size_t)row * NCODE;
        for (int j = lane; j < NCODE; j += 32) enc[j] = (j == idx) ? 1.0f : 0.0f;
        if (lane == 0) out[OFF_IDX + row] = (float)idx;
    }
}

__global__ void k_scalar(float* __restrict__ out) {
    __shared__ float sh[256];
    int t = threadIdx.x;
    float e = 0.0f;
    for (int c = t; c < NCODE; c += 256) {
        float p = (float)g_counts[c] * (1.0f / (float)NROWS);
        e += p * logf(p + 1e-10f);
    }
    sh[t] = e;
    __syncthreads();
    for (int s = 128; s > 0; s >>= 1) {
        if (t < s) sh[t] += sh[t + s];
        __syncthreads();
    }
    if (t == 0) {
        out[OFF_LOSS] = 0.25f * g_loss_sum / ((float)NROWS * (float)CDDIM);
        out[OFF_PERP] = expf(-sh[0]);
    }
}

// ---------------- launch ----------------
extern "C" void kernel_launch(void* const* d_in, const int* in_sizes, int n_in,
                              void* d_out, int out_size) {
    const float* states      = (const float*)d_in[0];
    const float* next_states = (const float*)d_in[1];
    const float* W_s         = (const float*)d_in[2];
    const float* b_s         = (const float*)d_in[3];
    const float* W_p         = (const float*)d_in[4];
    const float* b_p         = (const float*)d_in[5];
    const float* codebook    = (const float*)d_in[6];
    float* out = (float*)d_out;
    int full = (out_size >= OFF_ENC) ? 1 : 0;

    constexpr int SM_F16 = 4 * (64 * 32 + 128 * 32) * 4;    // 98304
    constexpr int SM_SC  = 2 * (64 * 32 + 256 * 32) * 4;    // 81920
    cudaFuncSetAttribute(gemm_f16<0, DDIM>,
                         cudaFuncAttributeMaxDynamicSharedMemorySize, SM_F16);
    cudaFuncSetAttribute(gemm_f16<1, 2 * EDIM>,
                         cudaFuncAttributeMaxDynamicSharedMemorySize, SM_F16);
    cudaFuncSetAttribute(gemm_score,
                         cudaFuncAttributeMaxDynamicSharedMemorySize, SM_SC);

    k_zero<<<1, 1024>>>();
    k_cnorm<<<4, 256>>>(codebook);

    // pre-split inputs to fp16 h/l
    const int spairs = NROWS * DDIM / 2;                     // 4.19M u32 per input
    k_split_rm<<<spairs / 256, 256>>>(states, 0, spairs);
    k_split_rm<<<spairs / 256, 256>>>(next_states, (uint32_t)spairs, spairs);
    k_split_tr<<<dim3(EDIM / 32, DDIM / 32), dim3(32, 8)>>>(W_s, DDIM, EDIM, 0);
    k_split_tr<<<dim3(CDDIM / 32, 2 * EDIM / 32), dim3(32, 8)>>>(W_p, 2 * EDIM, CDDIM, 1);

    // encoder: M=8192, N=2048, K=1024 (two inputs via grid.z) -> Hh/Hl
    gemm_f16<0, DDIM><<<dim3(EDIM / 128, NROWS / 64, 2), 256, SM_F16>>>(b_s);
    // policy head: M=8192, N=256, K=4096 -> latent (fp32)
    gemm_f16<1, 2 * EDIM><<<dim3(CDDIM / 128, NROWS / 64, 1), 256, SM_F16>>>(b_p);
    // scores: M=8192, N=1024 codes, K=256 (3x tf32)
    gemm_score<<<dim3(NCODE / 256, NROWS / 64), 256, SM_SC>>>(codebook);

    k_final<<<NROWS / 8, 256>>>(codebook, out, full);
    if (full) k_scalar<<<1, 256>>>(out);
}

// round 8
// speedup vs baseline: 2.7278x; 1.0885x over previous
#include <cuda_runtime.h>
#include <cuda_fp16.h>
#include <math.h>
#include <stdint.h>

// ---------------- problem constants ----------------
#define NROWS 8192     // B*T
#define DDIM  1024
#define EDIM  2048
#define CDDIM 256
#define NCODE 1024

// output layout (fp32 concat in reference return order)
#define OFF_Q     0
#define OFF_LOSS  2097152
#define OFF_PERP  2097153
#define OFF_ENC   2097154
#define OFF_IDX   10485762

// ---------------- scratch ----------------
__device__ uint32_t g_Sh[(size_t)2 * NROWS * (DDIM / 2)];      // states|next rows
__device__ uint32_t g_Sl[(size_t)2 * NROWS * (DDIM / 2)];
__device__ uint32_t g_Wsh[(size_t)EDIM * (DDIM / 2)];          // W_s^T  [E][D]
__device__ uint32_t g_Wsl[(size_t)EDIM * (DDIM / 2)];
__device__ uint32_t g_Wph[(size_t)CDDIM * (2 * EDIM / 2)];     // W_p^T  [CD][2E]
__device__ uint32_t g_Wpl[(size_t)CDDIM * (2 * EDIM / 2)];
__device__ uint32_t g_Hh[(size_t)NROWS * (2 * EDIM / 2)];      // H  [M][4096]
__device__ uint32_t g_Hl[(size_t)NROWS * (2 * EDIM / 2)];

__device__ float g_latent[(size_t)NROWS * CDDIM];
__device__ float g_cnorm[NCODE];
__device__ float g_pval[(size_t)NROWS * 16];
__device__ int   g_pidx[(size_t)NROWS * 16];
__device__ int   g_counts[NCODE];
__device__ float g_loss_sum;

// ---------------- helpers ----------------
__device__ __forceinline__ uint32_t smem_u32(const void* p) {
    uint32_t a;
    asm("{ .reg .u64 t; cvta.to.shared.u64 t, %1; cvt.u32.u64 %0, t; }" : "=r"(a) : "l"(p));
    return a;
}

#define CP16(dst, src) \
    asm volatile("cp.async.cg.shared.global [%0], [%1], 16;" :: "r"(dst), "l"(src))
#define CP_COMMIT() asm volatile("cp.async.commit_group;" ::: "memory")
template <int N>
__device__ __forceinline__ void cp_wait() {
    asm volatile("cp.async.wait_group %0;" :: "n"(N) : "memory");
}

__device__ __forceinline__ void ldm_x4(uint32_t* r, uint32_t addr) {
    asm volatile("ldmatrix.sync.aligned.m8n8.x4.shared.b16 {%0,%1,%2,%3}, [%4];"
                 : "=r"(r[0]), "=r"(r[1]), "=r"(r[2]), "=r"(r[3]) : "r"(addr));
}

// fp16 hi/lo split of an fp32 value
__device__ __forceinline__ void split_h(float v, uint16_t& h, uint16_t& l) {
    __half hh = __float2half_rn(v);
    float r = v - __half2float(hh);
    h = __half_as_ushort(hh);
    l = __half_as_ushort(__float2half_rn(r));
}

// tf32 split (score kernel)
__device__ __forceinline__ void split32(uint32_t u, uint32_t& h, uint32_t& l) {
    h = u & 0xffffe000u;
    l = __float_as_uint(__uint_as_float(u) - __uint_as_float(h));
}

// fp16 mma: D += A*B, m16n8k16, fp32 accumulate
__device__ __forceinline__ void mma16(float* c, const uint32_t* a, const uint32_t* b) {
    asm volatile(
        "mma.sync.aligned.m16n8k16.row.col.f32.f16.f16.f32 "
        "{%0,%1,%2,%3}, {%4,%5,%6,%7}, {%8,%9}, {%0,%1,%2,%3};"
        : "+f"(c[0]), "+f"(c[1]), "+f"(c[2]), "+f"(c[3])
        : "r"(a[0]), "r"(a[1]), "r"(a[2]), "r"(a[3]), "r"(b[0]), "r"(b[1]));
}

// tf32 mma: m16n8k8
__device__ __forceinline__ void mma8(float* c, const uint32_t* a, const uint32_t* b) {
    asm volatile(
        "mma.sync.aligned.m16n8k8.row.col.f32.tf32.tf32.f32 "
        "{%0,%1,%2,%3}, {%4,%5,%6,%7}, {%8,%9}, {%0,%1,%2,%3};"
        : "+f"(c[0]), "+f"(c[1]), "+f"(c[2]), "+f"(c[3])
        : "r"(a[0]), "r"(a[1]), "r"(a[2]), "r"(a[3]), "r"(b[0]), "r"(b[1]));
}

__device__ __forceinline__ float gelu_tanh(float x) {
    float x3 = x * x * x;
    float t  = tanhf(0.7978845608028654f * (x + 0.044715f * x3));
    return 0.5f * x * (1.0f + t);
}

// ---------------- pre-split kernels ----------------
__global__ void k_split_rm(const float* __restrict__ src, uint32_t off, int npairs) {
    int i = blockIdx.x * blockDim.x + threadIdx.x;
    if (i >= npairs) return;
    float2 v = ((const float2*)src)[i];
    uint16_t h0, l0, h1, l1;
    split_h(v.x, h0, l0);
    split_h(v.y, h1, l1);
    g_Sh[off + i] = (uint32_t)h0 | ((uint32_t)h1 << 16);
    g_Sl[off + i] = (uint32_t)l0 | ((uint32_t)l1 << 16);
}

// transpose [K][N] fp32 -> [N][K] fp16 h/l  (which: 0 = W_s, 1 = W_p)
__global__ void k_split_tr(const float* __restrict__ src, int K, int N, int which) {
    __shared__ float ts[32][33];
    int tx = threadIdx.x, ty = threadIdx.y;
    int n0 = blockIdx.x * 32, k0 = blockIdx.y * 32;
    #pragma unroll
    for (int r = 0; r < 4; r++)
        ts[ty + 8 * r][tx] = src[(size_t)(k0 + ty + 8 * r) * N + n0 + tx];
    __syncthreads();
    __half* dh = (__half*)(which ? g_Wph : g_Wsh);
    __half* dl = (__half*)(which ? g_Wpl : g_Wsl);
    #pragma unroll
    for (int r = 0; r < 4; r++) {
        int n = n0 + ty + 8 * r, k = k0 + tx;
        float v = ts[tx][ty + 8 * r];
        uint16_t h, l;
        split_h(v, h, l);
        dh[(size_t)n * K + k] = __ushort_as_half(h);
        dl[(size_t)n * K + k] = __ushort_as_half(l);
    }
}

// ---------------- fp16 split GEMM (ldmatrix inner loop) ----------------
// MODE 0: H = gelu(S @ Ws^T + b_s) -> g_Hh/g_Hl
// MODE 1: latent = H @ Wp^T + b_p  -> g_latent (fp32)
// CTA 64x128, 8 warps (2m x 4n), warp 32x32, K-chunk 32 halves, NSTG=4.
// smem stage: A 64 rows x 128B (chunks 0-3 hi k0..31, 4-7 lo), B 128 rows x 128B.
template <int MODE, int KT>
__global__ void __launch_bounds__(256, 2) gemm_f16(const float* __restrict__ bias) {
    extern __shared__ uint32_t smu[];
    constexpr int KW   = KT / 2;
    constexpr int NCH  = KT / 32;
    constexpr int ASZ  = 64 * 32;
    constexpr int BSZ  = 128 * 32;
    constexpr int STG  = ASZ + BSZ;
    constexpr int NSTG = 4;

    const uint32_t* Ah = (MODE == 0) ? g_Sh : g_Hh;
    const uint32_t* Al = (MODE == 0) ? g_Sl : g_Hl;
    const uint32_t* Bh = (MODE == 0) ? g_Wsh : g_Wph;
    const uint32_t* Bl = (MODE == 0) ? g_Wsl : g_Wpl;

    const int tid = threadIdx.x;
    const int wid = tid >> 5, lane = tid & 31;
    const int wm  = (wid & 1) * 32;
    const int wn  = (wid >> 1) * 32;
    const int lt  = lane & 3, lg = lane >> 2;

    const int m0 = blockIdx.y * 64, n0 = blockIdx.x * 128;
    const size_t arow0 = (MODE == 0) ? ((size_t)blockIdx.z * NROWS + m0) : (size_t)m0;
    const uint32_t sb = smem_u32(smu);

    // per-lane ldmatrix address components
    // A x4 for mt: matrices (rows, c), (rows+8, c), (rows, c+1), (rows+8, c+1)
    const int l7 = lane & 7;
    const int amrow0 = wm + l7 + 8 * ((lane >> 3) & 1);      // + 16*mt
    const uint32_t axk = ((lane >> 4) & 1) ^ l7;             // chunk xor field
    // B x4 for nt-pair p: matrices (nt=2p rows, c), (2p, c+1), (2p+1, c), (2p+1, c+1)
    const int bnrow0 = wn + l7 + 8 * ((lane >> 4) & 1);      // + 16*p
    const uint32_t bxk = ((lane >> 3) & 1) ^ l7;

    float acc[2][4][4];
    #pragma unroll
    for (int i = 0; i < 2; i++)
        #pragma unroll
        for (int j = 0; j < 4; j++)
            #pragma unroll
            for (int e = 0; e < 4; e++) acc[i][j][e] = 0.0f;

    auto copy_chunk = [&](int c, int stg) {
        const uint32_t dA = sb + stg * STG * 4;
        const uint32_t dB = dA + ASZ * 4;
        #pragma unroll
        for (int j = 0; j < 2; j++) {
            int u = tid + j * 256;
            int m = u >> 3, p = u & 7;
            const uint32_t* s = ((p < 4) ? Ah : Al)
                + (arow0 + m) * KW + c * 16 + (p & 3) * 4;
            uint32_t dst = dA + (m * 32 + ((p ^ (m & 7)) << 2)) * 4;
            CP16(dst, s);
        }
        #pragma unroll
        for (int j = 0; j < 4; j++) {
            int u = tid + j * 256;
            int n = u >> 3, p = u & 7;
            const uint32_t* s = ((p < 4) ? Bh : Bl)
                + (size_t)(n0 + n) * KW + c * 16 + (p & 3) * 4;
            uint32_t dst = dB + (n * 32 + ((p ^ (n & 7)) << 2)) * 4;
            CP16(dst, s);
        }
    };

    auto compute = [&](int stg) {
        const uint32_t sA = sb + stg * STG * 4;
        const uint32_t sB = sA + ASZ * 4;
        const uint32_t aBase0 = sA + (amrow0)      * 128;
        const uint32_t aBase1 = sA + (amrow0 + 16) * 128;
        const uint32_t bBase0 = sB + (bnrow0)      * 128;
        const uint32_t bBase1 = sB + (bnrow0 + 16) * 128;
        #pragma unroll
        for (int s = 0; s < 2; s++) {          // two k16 slabs
            const uint32_t ch = 2 * s;         // hi chunk base
            const uint32_t cl = 2 * s + 4;     // lo chunk base
            uint32_t ah[2][4], al[2][4];
            ldm_x4(ah[0], aBase0 + ((ch ^ axk) << 4));
            ldm_x4(al[0], aBase0 + ((cl ^ axk) << 4));
            ldm_x4(ah[1], aBase1 + ((ch ^ axk) << 4));
            ldm_x4(al[1], aBase1 + ((cl ^ axk) << 4));
            #pragma unroll
            for (int p = 0; p < 2; p++) {      // nt pairs (0,1) and (2,3)
                uint32_t bh[4], bl[4];
                const uint32_t bb = p ? bBase1 : bBase0;
                ldm_x4(bh, bb + ((ch ^ bxk) << 4));
                ldm_x4(bl, bb + ((cl ^ bxk) << 4));
                #pragma unroll
                for (int mt = 0; mt < 2; mt++) {
                    mma16(acc[mt][2 * p],     ah[mt], bh);       // hi*hi nt=2p
                    mma16(acc[mt][2 * p],     ah[mt], bl);       // hi*lo
                    mma16(acc[mt][2 * p],     al[mt], bh);       // lo*hi
                    mma16(acc[mt][2 * p + 1], ah[mt], bh + 2);   // nt=2p+1
                    mma16(acc[mt][2 * p + 1], ah[mt], bl + 2);
                    mma16(acc[mt][2 * p + 1], al[mt], bh + 2);
                }
            }
        }
    };

    // ---- prologue ----
    #pragma unroll
    for (int c = 0; c < NSTG - 1 && c < NCH; c++) { copy_chunk(c, c); CP_COMMIT(); }

    // ---- mainloop ----
    for (int c = 0; c < NCH; c++) {
        cp_wait<NSTG - 2>();
        __syncthreads();
        const int cn = c + NSTG - 1;
        if (cn < NCH) copy_chunk(cn, cn & (NSTG - 1));
        CP_COMMIT();
        compute(c & (NSTG - 1));
    }

    // ---- epilogue ----
    if (MODE == 0) {
        const int zoff = blockIdx.z ? EDIM : 0;
        #pragma unroll
        for (int mt = 0; mt < 2; mt++)
            #pragma unroll
            for (int h = 0; h < 2; h++) {
                const int row = m0 + wm + mt * 16 + lg + h * 8;
                #pragma unroll
                for (int nt = 0; nt < 4; nt++) {
                    const int col = wn + nt * 8 + 2 * lt;
                    float g0 = gelu_tanh(acc[mt][nt][h * 2 + 0] + bias[n0 + col]);
                    float g1 = gelu_tanh(acc[mt][nt][h * 2 + 1] + bias[n0 + col + 1]);
                    uint16_t h0, l0, h1, l1;
                    split_h(g0, h0, l0);
                    split_h(g1, h1, l1);
                    size_t cw = (size_t)row * (2 * EDIM / 2) + ((zoff + n0 + col) >> 1);
                    g_Hh[cw] = (uint32_t)h0 | ((uint32_t)h1 << 16);
                    g_Hl[cw] = (uint32_t)l0 | ((uint32_t)l1 << 16);
                }
            }
    } else {
        #pragma unroll
        for (int mt = 0; mt < 2; mt++)
            #pragma unroll
            for (int h = 0; h < 2; h++) {
                const int row = m0 + wm + mt * 16 + lg + h * 8;
                float* cr = g_latent + (size_t)row * CDDIM + n0;
                #pragma unroll
                for (int nt = 0; nt < 4; nt++) {
                    const int col = wn + nt * 8 + 2 * lt;
                    float2 o;
                    o.x = acc[mt][nt][h * 2 + 0] + bias[n0 + col];
                    o.y = acc[mt][nt][h * 2 + 1] + bias[n0 + col + 1];
                    *(float2*)(cr + col) = o;
                }
            }
    }
}

// ---------------- score GEMM (3x tf32) ----------------
__global__ void __launch_bounds__(256, 2) gemm_score(const float* __restrict__ CB) {
    extern __shared__ uint32_t smu[];
    constexpr int NCTA = 256, NNT = 8, NSTG = 2;
    constexpr int ASZ = 64 * 32, BSZ = NCTA * 32, STG_W = ASZ + BSZ;
    constexpr int NCH = CDDIM / 32;

    const int tid = threadIdx.x;
    const int wid = tid >> 5, lane = tid & 31;
    const int wm  = (wid & 1) * 32;
    const int wn  = (wid >> 1) * 64;
    const int lt  = lane & 3, lg = lane >> 2;

    const int m0 = blockIdx.y * 64, n0 = blockIdx.x * NCTA;
    const uint32_t sb = smem_u32(smu);

    float acc[2][NNT][4];
    #pragma unroll
    for (int i = 0; i < 2; i++)
        #pragma unroll
        for (int j = 0; j < NNT; j++)
            #pragma unroll
            for (int e = 0; e < 4; e++) acc[i][j][e] = 0.0f;

    auto copy_chunk = [&](int c, int stg) {
        const int k0 = c * 32;
        const uint32_t dA = sb + stg * STG_W * 4;
        const uint32_t dB = dA + ASZ * 4;
        #pragma unroll
        for (int j = 0; j < 2; j++) {
            int q = tid + j * 256;
            int m = q >> 3, ch = q & 7;
            const float* src = g_latent + (size_t)(m0 + m) * CDDIM + k0 + ch * 4;
            uint32_t dst = dA + (m * 32 + ((ch ^ (m & 7)) << 2)) * 4;
            CP16(dst, src);
        }
        #pragma unroll
        for (int j = 0; j < 8; j++) {
            int q = tid + j * 256;
            int n = q >> 3, ch = q & 7;
            const float* src = CB + (size_t)(n0 + n) * CDDIM + k0 + ch * 4;
            uint32_t dst = dB + (n * 32 + ((ch ^ (n & 7)) << 2)) * 4;
            CP16(dst, src);
        }
    };

    auto compute = [&](int stg) {
        const uint32_t* As = smu + stg * STG_W;
        const uint32_t* Bs = As + ASZ;
        #pragma unroll
        for (int s = 0; s < 4; s++) {
            uint32_t ah[2][4], al[2][4];
            #pragma unroll
            for (int mt = 0; mt < 2; mt++) {
                const int m = wm + mt * 16 + lg;
                const uint32_t* r0 = As + m * 32;
                const uint32_t* r1 = r0 + 8 * 32;
                const int c0 = (((2 * s)     ^ (m & 7)) << 2) + lt;
                const int c1 = (((2 * s + 1) ^ (m & 7)) << 2) + lt;
                split32(r0[c0], ah[mt][0], al[mt][0]);
                split32(r1[c0], ah[mt][1], al[mt][1]);
                split32(r0[c1], ah[mt][2], al[mt][2]);
                split32(r1[c1], ah[mt][3], al[mt][3]);
            }
            #pragma unroll
            for (int nt = 0; nt < NNT; nt++) {
                const int n = wn + nt * 8 + lg;
                const uint32_t* r = Bs + n * 32;
                const int c0 = (((2 * s)     ^ (n & 7)) << 2) + lt;
                const int c1 = (((2 * s + 1) ^ (n & 7)) << 2) + lt;
                uint32_t bh[2], bl[2];
                split32(r[c0], bh[0], bl[0]);
                split32(r[c1], bh[1], bl[1]);
                #pragma unroll
                for (int mt = 0; mt < 2; mt++) {
                    mma8(acc[mt][nt], ah[mt], bh);
                    mma8(acc[mt][nt], ah[mt], bl);
                    mma8(acc[mt][nt], al[mt], bh);
                }
            }
        }
    };

    #pragma unroll
    for (int c = 0; c < NSTG - 1 && c < NCH; c++) { copy_chunk(c, c); CP_COMMIT(); }
    for (int c = 0; c < NCH; c++) {
        cp_wait<NSTG - 2>();
        __syncthreads();
        const int cn = c + NSTG - 1;
        if (cn < NCH) copy_chunk(cn, cn & (NSTG - 1));
        CP_COMMIT();
        compute(c & (NSTG - 1));
    }

    #pragma unroll
    for (int mt = 0; mt < 2; mt++)
        #pragma unroll
        for (int h = 0; h < 2; h++) {
            const int row = m0 + wm + mt * 16 + lg + h * 8;
            float best = INFINITY; int bi = 0;
            #pragma unroll
            for (int nt = 0; nt < NNT; nt++)
                #pragma unroll
                for (int e = 0; e < 2; e++) {
                    const int col = n0 + wn + nt * 8 + 2 * lt + e;
                    float s = g_cnorm[col] - 2.0f * acc[mt][nt][h * 2 + e];
                    if (s < best) { best = s; bi = col; }
                }
            #pragma unroll
            for (int msk = 1; msk <= 2; msk <<= 1) {
                float ov = __shfl_xor_sync(0xffffffffu, best, msk);
                int   oi = __shfl_xor_sync(0xffffffffu, bi,   msk);
                if (ov < best || (ov == best && oi < bi)) { best = ov; bi = oi; }
            }
            if (lt == 0) {
                g_pval[(size_t)row * 16 + blockIdx.x * 4 + (wid >> 1)] = best;
                g_pidx[(size_t)row * 16 + blockIdx.x * 4 + (wid >> 1)] = bi;
            }
        }
}

// ---------------- small kernels ----------------
__global__ void k_zero() {
    int t = threadIdx.x;
    if (t < NCODE) g_counts[t] = 0;
    if (t == 0)    g_loss_sum = 0.0f;
}

__global__ void k_cnorm(const float* __restrict__ cb) {
    int c = blockIdx.x * blockDim.x + threadIdx.x;
    if (c < NCODE) {
        float s = 0.0f;
        const float* row = cb + (size_t)c * CDDIM;
        #pragma unroll 8
        for (int k = 0; k < CDDIM; k++) { float v = row[k]; s += v * v; }
        g_cnorm[c] = s;
    }
}

__global__ __launch_bounds__(256) void k_final(const float* __restrict__ CB,
                                               float* __restrict__ out, int full) {
    const int warp = threadIdx.x >> 5, lane = threadIdx.x & 31;
    const int row = blockIdx.x * 8 + warp;

    float v = INFINITY; int ii = 0x7fffffff;
    if (lane < 16) { v = g_pval[(size_t)row * 16 + lane]; ii = g_pidx[(size_t)row * 16 + lane]; }
    #pragma unroll
    for (int off = 16; off > 0; off >>= 1) {
        float ov = __shfl_down_sync(0xffffffffu, v, off);
        int   oi = __shfl_down_sync(0xffffffffu, ii, off);
        if (ov < v || (ov == v && oi < ii)) { v = ov; ii = oi; }
    }
    int idx = __shfl_sync(0xffffffffu, ii, 0);

    float ls = 0.0f;
    for (int j = lane; j < CDDIM; j += 32) {
        float c = CB[(size_t)idx * CDDIM + j];
        float l = g_latent[(size_t)row * CDDIM + j];
        out[OFF_Q + (size_t)row * CDDIM + j] = c;
        float d = c - l; ls += d * d;
    }
    #pragma unroll
    for (int off = 16; off > 0; off >>= 1)
        ls += __shfl_down_sync(0xffffffffu, ls, off);
    if (lane == 0) {
        atomicAdd(&g_loss_sum, ls);
        atomicAdd(&g_counts[idx], 1);
    }
    if (full) {
        float* enc = out + OFF_ENC + (size_t)row * NCODE;
        for (int j = lane; j < NCODE; j += 32) enc[j] = (j == idx) ? 1.0f : 0.0f;
        if (lane == 0) out[OFF_IDX + row] = (float)idx;
    }
}

__global__ void k_scalar(float* __restrict__ out) {
    __shared__ float sh[256];
    int t = threadIdx.x;
    float e = 0.0f;
    for (int c = t; c < NCODE; c += 256) {
        float p = (float)g_counts[c] * (1.0f / (float)NROWS);
        e += p * logf(p + 1e-10f);
    }
    sh[t] = e;
    __syncthreads();
    for (int s = 128; s > 0; s >>= 1) {
        if (t < s) sh[t] += sh[t + s];
        __syncthreads();
    }
    if (t == 0) {
        out[OFF_LOSS] = 0.25f * g_loss_sum / ((float)NROWS * (float)CDDIM);
        out[OFF_PERP] = expf(-sh[0]);
    }
}

// ---------------- launch ----------------
extern "C" void kernel_launch(void* const* d_in, const int* in_sizes, int n_in,
                              void* d_out, int out_size) {
    const float* states      = (const float*)d_in[0];
    const float* next_states = (const float*)d_in[1];
    const float* W_s         = (const float*)d_in[2];
    const float* b_s         = (const float*)d_in[3];
    const float* W_p         = (const float*)d_in[4];
    const float* b_p         = (const float*)d_in[5];
    const float* codebook    = (const float*)d_in[6];
    float* out = (float*)d_out;
    int full = (out_size >= OFF_ENC) ? 1 : 0;

    constexpr int SM_F16 = 4 * (64 * 32 + 128 * 32) * 4;    // 98304
    constexpr int SM_SC  = 2 * (64 * 32 + 256 * 32) * 4;    // 81920
    cudaFuncSetAttribute(gemm_f16<0, DDIM>,
                         cudaFuncAttributeMaxDynamicSharedMemorySize, SM_F16);
    cudaFuncSetAttribute(gemm_f16<1, 2 * EDIM>,
                         cudaFuncAttributeMaxDynamicSharedMemorySize, SM_F16);
    cudaFuncSetAttribute(gemm_score,
                         cudaFuncAttributeMaxDynamicSharedMemorySize, SM_SC);

    k_zero<<<1, 1024>>>();
    k_cnorm<<<4, 256>>>(codebook);

    const int spairs = NROWS * DDIM / 2;
    k_split_rm<<<spairs / 256, 256>>>(states, 0, spairs);
    k_split_rm<<<spairs / 256, 256>>>(next_states, (uint32_t)spairs, spairs);
    k_split_tr<<<dim3(EDIM / 32, DDIM / 32), dim3(32, 8)>>>(W_s, DDIM, EDIM, 0);
    k_split_tr<<<dim3(CDDIM / 32, 2 * EDIM / 32), dim3(32, 8)>>>(W_p, 2 * EDIM, CDDIM, 1);

    gemm_f16<0, DDIM><<<dim3(EDIM / 128, NROWS / 64, 2), 256, SM_F16>>>(b_s);
    gemm_f16<1, 2 * EDIM><<<dim3(CDDIM / 128, NROWS / 64, 1), 256, SM_F16>>>(b_p);
    gemm_score<<<dim3(NCODE / 256, NROWS / 64), 256, SM_SC>>>(codebook);

    k_final<<<NROWS / 8, 256>>>(codebook, out, full);
    if (full) k_scalar<<<1, 256>>>(out);
}

// round 9
// speedup vs baseline: 2.8344x; 1.0391x over previous
#include <cuda_runtime.h>
#include <cuda_fp16.h>
#include <math.h>
#include <stdint.h>

// ---------------- problem constants ----------------
#define NROWS 8192     // B*T
#define DDIM  1024
#define EDIM  2048
#define CDDIM 256
#define NCODE 1024

// output layout (fp32 concat in reference return order)
#define OFF_Q     0
#define OFF_LOSS  2097152
#define OFF_PERP  2097153
#define OFF_ENC   2097154
#define OFF_IDX   10485762

// ---------------- scratch ----------------
__device__ uint32_t g_Sh[(size_t)2 * NROWS * (DDIM / 2)];      // states|next rows
__device__ uint32_t g_Sl[(size_t)2 * NROWS * (DDIM / 2)];
__device__ uint32_t g_Wsh[(size_t)EDIM * (DDIM / 2)];          // W_s^T  [E][D]
__device__ uint32_t g_Wsl[(size_t)EDIM * (DDIM / 2)];
__device__ uint32_t g_Wph[(size_t)CDDIM * (2 * EDIM / 2)];     // W_p^T  [CD][2E]
__device__ uint32_t g_Wpl[(size_t)CDDIM * (2 * EDIM / 2)];
__device__ uint32_t g_Hh[(size_t)NROWS * (2 * EDIM / 2)];      // H  [M][4096]
__device__ uint32_t g_Hl[(size_t)NROWS * (2 * EDIM / 2)];
__device__ uint32_t g_Lh[(size_t)NROWS * (CDDIM / 2)];         // latent fp16 h/l
__device__ uint32_t g_Ll[(size_t)NROWS * (CDDIM / 2)];
__device__ uint32_t g_Ch[(size_t)NCODE * (CDDIM / 2)];         // codebook fp16 h/l
__device__ uint32_t g_Cl[(size_t)NCODE * (CDDIM / 2)];

__device__ float g_latent[(size_t)NROWS * CDDIM];
__device__ float g_cnorm[NCODE];
__device__ float g_pval[(size_t)NROWS * 32];
__device__ int   g_pidx[(size_t)NROWS * 32];
__device__ int   g_counts[NCODE];
__device__ float g_loss_sum;

// ---------------- helpers ----------------
__device__ __forceinline__ uint32_t smem_u32(const void* p) {
    uint32_t a;
    asm("{ .reg .u64 t; cvta.to.shared.u64 t, %1; cvt.u32.u64 %0, t; }" : "=r"(a) : "l"(p));
    return a;
}

#define CP16(dst, src) \
    asm volatile("cp.async.cg.shared.global [%0], [%1], 16;" :: "r"(dst), "l"(src))
#define CP_COMMIT() asm volatile("cp.async.commit_group;" ::: "memory")
template <int N>
__device__ __forceinline__ void cp_wait() {
    asm volatile("cp.async.wait_group %0;" :: "n"(N) : "memory");
}

__device__ __forceinline__ void ldm_x4(uint32_t* r, uint32_t addr) {
    asm volatile("ldmatrix.sync.aligned.m8n8.x4.shared.b16 {%0,%1,%2,%3}, [%4];"
                 : "=r"(r[0]), "=r"(r[1]), "=r"(r[2]), "=r"(r[3]) : "r"(addr));
}

// fp16 hi/lo split of an fp32 value
__device__ __forceinline__ void split_h(float v, uint16_t& h, uint16_t& l) {
    __half hh = __float2half_rn(v);
    float r = v - __half2float(hh);
    h = __half_as_ushort(hh);
    l = __half_as_ushort(__float2half_rn(r));
}

// fp16 mma: D += A*B, m16n8k16, fp32 accumulate
__device__ __forceinline__ void mma16(float* c, const uint32_t* a, const uint32_t* b) {
    asm volatile(
        "mma.sync.aligned.m16n8k16.row.col.f32.f16.f16.f32 "
        "{%0,%1,%2,%3}, {%4,%5,%6,%7}, {%8,%9}, {%0,%1,%2,%3};"
        : "+f"(c[0]), "+f"(c[1]), "+f"(c[2]), "+f"(c[3])
        : "r"(a[0]), "r"(a[1]), "r"(a[2]), "r"(a[3]), "r"(b[0]), "r"(b[1]));
}

__device__ __forceinline__ float gelu_tanh(float x) {
    float x3 = x * x * x;
    float t  = tanhf(0.7978845608028654f * (x + 0.044715f * x3));
    return 0.5f * x * (1.0f + t);
}

// ---------------- prep / split kernels ----------------
// zero accumulators + codebook norms (exact fp32)
__global__ void k_prep(const float* __restrict__ cb) {
    int c = blockIdx.x * blockDim.x + threadIdx.x;
    if (c < NCODE) {
        g_counts[c] = 0;
        float s = 0.0f;
        const float* row = cb + (size_t)c * CDDIM;
        #pragma unroll 8
        for (int k = 0; k < CDDIM; k++) { float v = row[k]; s += v * v; }
        g_cnorm[c] = s;
    }
    if (c == 0) g_loss_sum = 0.0f;
}

__global__ void k_split_rm(const float* __restrict__ src, uint32_t off, int npairs) {
    int i = blockIdx.x * blockDim.x + threadIdx.x;
    if (i >= npairs) return;
    float2 v = ((const float2*)src)[i];
    uint16_t h0, l0, h1, l1;
    split_h(v.x, h0, l0);
    split_h(v.y, h1, l1);
    g_Sh[off + i] = (uint32_t)h0 | ((uint32_t)h1 << 16);
    g_Sl[off + i] = (uint32_t)l0 | ((uint32_t)l1 << 16);
}

// codebook [n][k] row-major fp32 -> packed fp16 h/l
__global__ void k_split_cb(const float* __restrict__ src, int npairs) {
    int i = blockIdx.x * blockDim.x + threadIdx.x;
    if (i >= npairs) return;
    float2 v = ((const float2*)src)[i];
    uint16_t h0, l0, h1, l1;
    split_h(v.x, h0, l0);
    split_h(v.y, h1, l1);
    g_Ch[i] = (uint32_t)h0 | ((uint32_t)h1 << 16);
    g_Cl[i] = (uint32_t)l0 | ((uint32_t)l1 << 16);
}

// transpose [K][N] fp32 -> [N][K] fp16 h/l  (which: 0 = W_s, 1 = W_p)
__global__ void k_split_tr(const float* __restrict__ src, int K, int N, int which) {
    __shared__ float ts[32][33];
    int tx = threadIdx.x, ty = threadIdx.y;
    int n0 = blockIdx.x * 32, k0 = blockIdx.y * 32;
    #pragma unroll
    for (int r = 0; r < 4; r++)
        ts[ty + 8 * r][tx] = src[(size_t)(k0 + ty + 8 * r) * N + n0 + tx];
    __syncthreads();
    __half* dh = (__half*)(which ? g_Wph : g_Wsh);
    __half* dl = (__half*)(which ? g_Wpl : g_Wsl);
    #pragma unroll
    for (int r = 0; r < 4; r++) {
        int n = n0 + ty + 8 * r, k = k0 + tx;
        float v = ts[tx][ty + 8 * r];
        uint16_t h, l;
        split_h(v, h, l);
        dh[(size_t)n * K + k] = __ushort_as_half(h);
        dl[(size_t)n * K + k] = __ushort_as_half(l);
    }
}

// ---------------- fp16 split GEMM (ldmatrix inner loop) ----------------
// MODE 0: H = gelu(S @ Ws^T + b_s) -> g_Hh/g_Hl
// MODE 1: latent = H @ Wp^T + b_p  -> g_latent (fp32) + g_Lh/g_Ll
// MODE 2: scores = latent . CB^T   -> per-warp partial argmin
// CTA 64x128, 8 warps (2m x 4n), warp 32x32, K-chunk 32 halves, NSTG=4.
template <int MODE, int KT>
__global__ void __launch_bounds__(256, 2) gemm_f16(const float* __restrict__ bias) {
    extern __shared__ uint32_t smu[];
    constexpr int KW   = KT / 2;
    constexpr int NCH  = KT / 32;
    constexpr int ASZ  = 64 * 32;
    constexpr int BSZ  = 128 * 32;
    constexpr int STG  = ASZ + BSZ;
    constexpr int NSTG = 4;

    const uint32_t* Ah = (MODE == 0) ? g_Sh : (MODE == 1) ? g_Hh : g_Lh;
    const uint32_t* Al = (MODE == 0) ? g_Sl : (MODE == 1) ? g_Hl : g_Ll;
    const uint32_t* Bh = (MODE == 0) ? g_Wsh : (MODE == 1) ? g_Wph : g_Ch;
    const uint32_t* Bl = (MODE == 0) ? g_Wsl : (MODE == 1) ? g_Wpl : g_Cl;

    const int tid = threadIdx.x;
    const int wid = tid >> 5, lane = tid & 31;
    const int wm  = (wid & 1) * 32;
    const int wn  = (wid >> 1) * 32;
    const int lt  = lane & 3, lg = lane >> 2;

    const int m0 = blockIdx.y * 64, n0 = blockIdx.x * 128;
    const size_t arow0 = (MODE == 0) ? ((size_t)blockIdx.z * NROWS + m0) : (size_t)m0;
    const uint32_t sb = smem_u32(smu);

    // per-lane ldmatrix address components
    const int l7 = lane & 7;
    const int amrow0 = wm + l7 + 8 * ((lane >> 3) & 1);      // + 16*mt
    const uint32_t axk = ((lane >> 4) & 1) ^ l7;
    const int bnrow0 = wn + l7 + 8 * ((lane >> 4) & 1);      // + 16*p
    const uint32_t bxk = ((lane >> 3) & 1) ^ l7;

    float acc[2][4][4];
    #pragma unroll
    for (int i = 0; i < 2; i++)
        #pragma unroll
        for (int j = 0; j < 4; j++)
            #pragma unroll
            for (int e = 0; e < 4; e++) acc[i][j][e] = 0.0f;

    auto copy_chunk = [&](int c, int stg) {
        const uint32_t dA = sb + stg * STG * 4;
        const uint32_t dB = dA + ASZ * 4;
        #pragma unroll
        for (int j = 0; j < 2; j++) {
            int u = tid + j * 256;
            int m = u >> 3, p = u & 7;
            const uint32_t* s = ((p < 4) ? Ah : Al)
                + (arow0 + m) * KW + c * 16 + (p & 3) * 4;
            uint32_t dst = dA + (m * 32 + ((p ^ (m & 7)) << 2)) * 4;
            CP16(dst, s);
        }
        #pragma unroll
        for (int j = 0; j < 4; j++) {
            int u = tid + j * 256;
            int n = u >> 3, p = u & 7;
            const uint32_t* s = ((p < 4) ? Bh : Bl)
                + (size_t)(n0 + n) * KW + c * 16 + (p & 3) * 4;
            uint32_t dst = dB + (n * 32 + ((p ^ (n & 7)) << 2)) * 4;
            CP16(dst, s);
        }
    };

    auto compute = [&](int stg) {
        const uint32_t sA = sb + stg * STG * 4;
        const uint32_t sB = sA + ASZ * 4;
        const uint32_t aBase0 = sA + (amrow0)      * 128;
        const uint32_t aBase1 = sA + (amrow0 + 16) * 128;
        const uint32_t bBase0 = sB + (bnrow0)      * 128;
        const uint32_t bBase1 = sB + (bnrow0 + 16) * 128;
        #pragma unroll
        for (int s = 0; s < 2; s++) {
            const uint32_t ch = 2 * s;
            const uint32_t cl = 2 * s + 4;
            uint32_t ah[2][4], al[2][4];
            ldm_x4(ah[0], aBase0 + ((ch ^ axk) << 4));
            ldm_x4(al[0], aBase0 + ((cl ^ axk) << 4));
            ldm_x4(ah[1], aBase1 + ((ch ^ axk) << 4));
            ldm_x4(al[1], aBase1 + ((cl ^ axk) << 4));
            #pragma unroll
            for (int p = 0; p < 2; p++) {
                uint32_t bh[4], bl[4];
                const uint32_t bb = p ? bBase1 : bBase0;
                ldm_x4(bh, bb + ((ch ^ bxk) << 4));
                ldm_x4(bl, bb + ((cl ^ bxk) << 4));
                #pragma unroll
                for (int mt = 0; mt < 2; mt++) {
                    mma16(acc[mt][2 * p],     ah[mt], bh);
                    mma16(acc[mt][2 * p],     ah[mt], bl);
                    mma16(acc[mt][2 * p],     al[mt], bh);
                    mma16(acc[mt][2 * p + 1], ah[mt], bh + 2);
                    mma16(acc[mt][2 * p + 1], ah[mt], bl + 2);
                    mma16(acc[mt][2 * p + 1], al[mt], bh + 2);
                }
            }
        }
    };

    // ---- prologue ----
    #pragma unroll
    for (int c = 0; c < NSTG - 1 && c < NCH; c++) { copy_chunk(c, c); CP_COMMIT(); }

    // ---- mainloop ----
    for (int c = 0; c < NCH; c++) {
        cp_wait<NSTG - 2>();
        __syncthreads();
        const int cn = c + NSTG - 1;
        if (cn < NCH) copy_chunk(cn, cn & (NSTG - 1));
        CP_COMMIT();
        compute(c & (NSTG - 1));
    }

    // ---- epilogue ----
    if (MODE == 0) {
        const int zoff = blockIdx.z ? EDIM : 0;
        #pragma unroll
        for (int mt = 0; mt < 2; mt++)
            #pragma unroll
            for (int h = 0; h < 2; h++) {
                const int row = m0 + wm + mt * 16 + lg + h * 8;
                #pragma unroll
                for (int nt = 0; nt < 4; nt++) {
                    const int col = wn + nt * 8 + 2 * lt;
                    float g0 = gelu_tanh(acc[mt][nt][h * 2 + 0] + bias[n0 + col]);
                    float g1 = gelu_tanh(acc[mt][nt][h * 2 + 1] + bias[n0 + col + 1]);
                    uint16_t h0, l0, h1, l1;
                    split_h(g0, h0, l0);
                    split_h(g1, h1, l1);
                    size_t cw = (size_t)row * (2 * EDIM / 2) + ((zoff + n0 + col) >> 1);
                    g_Hh[cw] = (uint32_t)h0 | ((uint32_t)h1 << 16);
                    g_Hl[cw] = (uint32_t)l0 | ((uint32_t)l1 << 16);
                }
            }
    } else if (MODE == 1) {
        #pragma unroll
        for (int mt = 0; mt < 2; mt++)
            #pragma unroll
            for (int h = 0; h < 2; h++) {
                const int row = m0 + wm + mt * 16 + lg + h * 8;
                #pragma unroll
                for (int nt = 0; nt < 4; nt++) {
                    const int col = wn + nt * 8 + 2 * lt;
                    float v0 = acc[mt][nt][h * 2 + 0] + bias[n0 + col];
                    float v1 = acc[mt][nt][h * 2 + 1] + bias[n0 + col + 1];
                    float2 o; o.x = v0; o.y = v1;
                    *(float2*)(g_latent + (size_t)row * CDDIM + n0 + col) = o;
                    uint16_t h0, l0, h1, l1;
                    split_h(v0, h0, l0);
                    split_h(v1, h1, l1);
                    size_t cw = (size_t)row * (CDDIM / 2) + ((n0 + col) >> 1);
                    g_Lh[cw] = (uint32_t)h0 | ((uint32_t)h1 << 16);
                    g_Ll[cw] = (uint32_t)l0 | ((uint32_t)l1 << 16);
                }
            }
    } else {
        // per-warp partial argmin over its 32 codes
        #pragma unroll
        for (int mt = 0; mt < 2; mt++)
            #pragma unroll
            for (int h = 0; h < 2; h++) {
                const int row = m0 + wm + mt * 16 + lg + h * 8;
                float best = INFINITY; int bi = 0;
                #pragma unroll
                for (int nt = 0; nt < 4; nt++)
                    #pragma unroll
                    for (int e = 0; e < 2; e++) {
                        const int col = n0 + wn + nt * 8 + 2 * lt + e;
                        float s = g_cnorm[col] - 2.0f * acc[mt][nt][h * 2 + e];
                        if (s < best) { best = s; bi = col; }
                    }
                #pragma unroll
                for (int msk = 1; msk <= 2; msk <<= 1) {
                    float ov = __shfl_xor_sync(0xffffffffu, best, msk);
                    int   oi = __shfl_xor_sync(0xffffffffu, bi,   msk);
                    if (ov < best || (ov == best && oi < bi)) { best = ov; bi = oi; }
                }
                if (lt == 0) {
                    g_pval[(size_t)row * 32 + blockIdx.x * 4 + (wid >> 1)] = best;
                    g_pidx[(size_t)row * 32 + blockIdx.x * 4 + (wid >> 1)] = bi;
                }
            }
    }
}

// ---------------- finalize ----------------
__global__ __launch_bounds__(256) void k_final(const float* __restrict__ CB,
                                               float* __restrict__ out, int full) {
    const int warp = threadIdx.x >> 5, lane = threadIdx.x & 31;
    const int row = blockIdx.x * 8 + warp;

    float v = g_pval[(size_t)row * 32 + lane];
    int  ii = g_pidx[(size_t)row * 32 + lane];
    #pragma unroll
    for (int off = 16; off > 0; off >>= 1) {
        float ov = __shfl_down_sync(0xffffffffu, v, off);
        int   oi = __shfl_down_sync(0xffffffffu, ii, off);
        if (ov < v || (ov == v && oi < ii)) { v = ov; ii = oi; }
    }
    int idx = __shfl_sync(0xffffffffu, ii, 0);

    float ls = 0.0f;
    for (int j = lane; j < CDDIM; j += 32) {
        float c = CB[(size_t)idx * CDDIM + j];
        float l = g_latent[(size_t)row * CDDIM + j];
        out[OFF_Q + (size_t)row * CDDIM + j] = c;
        float d = c - l; ls += d * d;
    }
    #pragma unroll
    for (int off = 16; off > 0; off >>= 1)
        ls += __shfl_down_sync(0xffffffffu, ls, off);
    if (lane == 0) {
        atomicAdd(&g_loss_sum, ls);
        atomicAdd(&g_counts[idx], 1);
    }
    if (full) {
        float* enc = out + OFF_ENC + (size_t)row * NCODE;
        for (int j = lane; j < NCODE; j += 32) enc[j] = (j == idx) ? 1.0f : 0.0f;
        if (lane == 0) out[OFF_IDX + row] = (float)idx;
    }
}

__global__ void k_scalar(float* __restrict__ out) {
    __shared__ float sh[256];
    int t = threadIdx.x;
    float e = 0.0f;
    for (int c = t; c < NCODE; c += 256) {
        float p = (float)g_counts[c] * (1.0f / (float)NROWS);
        e += p * logf(p + 1e-10f);
    }
    sh[t] = e;
    __syncthreads();
    for (int s = 128; s > 0; s >>= 1) {
        if (t < s) sh[t] += sh[t + s];
        __syncthreads();
    }
    if (t == 0) {
        out[OFF_LOSS] = 0.25f * g_loss_sum / ((float)NROWS * (float)CDDIM);
        out[OFF_PERP] = expf(-sh[0]);
    }
}

// ---------------- launch ----------------
extern "C" void kernel_launch(void* const* d_in, const int* in_sizes, int n_in,
                              void* d_out, int out_size) {
    const float* states      = (const float*)d_in[0];
    const float* next_states = (const float*)d_in[1];
    const float* W_s         = (const float*)d_in[2];
    const float* b_s         = (const float*)d_in[3];
    const float* W_p         = (const float*)d_in[4];
    const float* b_p         = (const float*)d_in[5];
    const float* codebook    = (const float*)d_in[6];
    float* out = (float*)d_out;
    int full = (out_size >= OFF_ENC) ? 1 : 0;

    constexpr int SM_F16 = 4 * (64 * 32 + 128 * 32) * 4;    // 98304
    cudaFuncSetAttribute(gemm_f16<0, DDIM>,
                         cudaFuncAttributeMaxDynamicSharedMemorySize, SM_F16);
    cudaFuncSetAttribute(gemm_f16<1, 2 * EDIM>,
                         cudaFuncAttributeMaxDynamicSharedMemorySize, SM_F16);
    cudaFuncSetAttribute(gemm_f16<2, CDDIM>,
                         cudaFuncAttributeMaxDynamicSharedMemorySize, SM_F16);

    k_prep<<<4, 256>>>(codebook);

    const int spairs = NROWS * DDIM / 2;
    k_split_rm<<<spairs / 256, 256>>>(states, 0, spairs);
    k_split_rm<<<spairs / 256, 256>>>(next_states, (uint32_t)spairs, spairs);
    k_split_tr<<<dim3(EDIM / 32, DDIM / 32), dim3(32, 8)>>>(W_s, DDIM, EDIM, 0);
    k_split_tr<<<dim3(CDDIM / 32, 2 * EDIM / 32), dim3(32, 8)>>>(W_p, 2 * EDIM, CDDIM, 1);
    k_split_cb<<<NCODE * CDDIM / 2 / 256, 256>>>(codebook, NCODE * CDDIM / 2);

    // encoder: M=8192, N=2048, K=1024 (two inputs via grid.z) -> Hh/Hl
    gemm_f16<0, DDIM><<<dim3(EDIM / 128, NROWS / 64, 2), 256, SM_F16>>>(b_s);
    // policy head: M=8192, N=256, K=4096 -> latent fp32 + fp16 h/l
    gemm_f16<1, 2 * EDIM><<<dim3(CDDIM / 128, NROWS / 64, 1), 256, SM_F16>>>(b_p);
    // scores: M=8192, N=1024 codes, K=256 (fp16 split)
    gemm_f16<2, CDDIM><<<dim3(NCODE / 128, NROWS / 64, 1), 256, SM_F16>>>(nullptr);

    k_final<<<NROWS / 8, 256>>>(codebook, out, full);
    if (full) k_scalar<<<1, 256>>>(out);
}

// round 10
// speedup vs baseline: 2.9909x; 1.0552x over previous
#include <cuda_runtime.h>
#include <cuda_fp16.h>
#include <math.h>
#include <stdint.h>

// ---------------- problem constants ----------------
#define NROWS 8192     // B*T
#define DDIM  1024
#define EDIM  2048
#define CDDIM 256
#define NCODE 1024

// output layout (fp32 concat in reference return order)
#define OFF_Q     0
#define OFF_LOSS  2097152
#define OFF_PERP  2097153
#define OFF_ENC   2097154
#define OFF_IDX   10485762

// ---------------- scratch ----------------
__device__ uint32_t g_Sh[(size_t)2 * NROWS * (DDIM / 2)];      // states|next rows
__device__ uint32_t g_Sl[(size_t)2 * NROWS * (DDIM / 2)];
__device__ uint32_t g_Wsh[(size_t)EDIM * (DDIM / 2)];          // W_s^T  [E][D]
__device__ uint32_t g_Wsl[(size_t)EDIM * (DDIM / 2)];
__device__ uint32_t g_Wph[(size_t)CDDIM * (2 * EDIM / 2)];     // W_p^T  [CD][2E]
__device__ uint32_t g_Wpl[(size_t)CDDIM * (2 * EDIM / 2)];
__device__ uint32_t g_Hh[(size_t)NROWS * (2 * EDIM / 2)];      // H  [M][4096]
__device__ uint32_t g_Hl[(size_t)NROWS * (2 * EDIM / 2)];
__device__ uint32_t g_Lh[(size_t)NROWS * (CDDIM / 2)];         // latent fp16 h/l
__device__ uint32_t g_Ll[(size_t)NROWS * (CDDIM / 2)];
__device__ uint32_t g_Ch[(size_t)NCODE * (CDDIM / 2)];         // codebook fp16 h/l
__device__ uint32_t g_Cl[(size_t)NCODE * (CDDIM / 2)];

__device__ float g_latent[(size_t)NROWS * CDDIM];
__device__ float g_cnorm[NCODE];
__device__ float g_pval[(size_t)NROWS * 16];
__device__ int   g_pidx[(size_t)NROWS * 16];
__device__ int   g_counts[NCODE];
__device__ float g_loss_sum;

// ---------------- helpers ----------------
__device__ __forceinline__ uint32_t smem_u32(const void* p) {
    uint32_t a;
    asm("{ .reg .u64 t; cvta.to.shared.u64 t, %1; cvt.u32.u64 %0, t; }" : "=r"(a) : "l"(p));
    return a;
}

#define CP16(dst, src) \
    asm volatile("cp.async.cg.shared.global [%0], [%1], 16;" :: "r"(dst), "l"(src))
#define CP_COMMIT() asm volatile("cp.async.commit_group;" ::: "memory")
template <int N>
__device__ __forceinline__ void cp_wait() {
    asm volatile("cp.async.wait_group %0;" :: "n"(N) : "memory");
}

__device__ __forceinline__ void ldm_x4(uint32_t* r, uint32_t addr) {
    asm volatile("ldmatrix.sync.aligned.m8n8.x4.shared.b16 {%0,%1,%2,%3}, [%4];"
                 : "=r"(r[0]), "=r"(r[1]), "=r"(r[2]), "=r"(r[3]) : "r"(addr));
}

// fp16 hi/lo split of an fp32 value
__device__ __forceinline__ void split_h(float v, uint16_t& h, uint16_t& l) {
    __half hh = __float2half_rn(v);
    float r = v - __half2float(hh);
    h = __half_as_ushort(hh);
    l = __half_as_ushort(__float2half_rn(r));
}

// fp16 mma: D += A*B, m16n8k16, fp32 accumulate
__device__ __forceinline__ void mma16(float* c, const uint32_t* a, const uint32_t* b) {
    asm volatile(
        "mma.sync.aligned.m16n8k16.row.col.f32.f16.f16.f32 "
        "{%0,%1,%2,%3}, {%4,%5,%6,%7}, {%8,%9}, {%0,%1,%2,%3};"
        : "+f"(c[0]), "+f"(c[1]), "+f"(c[2]), "+f"(c[3])
        : "r"(a[0]), "r"(a[1]), "r"(a[2]), "r"(a[3]), "r"(b[0]), "r"(b[1]));
}

__device__ __forceinline__ float gelu_tanh(float x) {
    float x3 = x * x * x;
    float t  = tanhf(0.7978845608028654f * (x + 0.044715f * x3));
    return 0.5f * x * (1.0f + t);
}

// ---------------- prep / split kernels ----------------
__global__ void k_prep(const float* __restrict__ cb) {
    int c = blockIdx.x * blockDim.x + threadIdx.x;
    if (c < NCODE) {
        g_counts[c] = 0;
        float s = 0.0f;
        const float* row = cb + (size_t)c * CDDIM;
        #pragma unroll 8
        for (int k = 0; k < CDDIM; k++) { float v = row[k]; s += v * v; }
        g_cnorm[c] = s;
    }
    if (c == 0) g_loss_sum = 0.0f;
}

__global__ void k_split_rm(const float* __restrict__ src, uint32_t off, int npairs) {
    int i = blockIdx.x * blockDim.x + threadIdx.x;
    if (i >= npairs) return;
    float2 v = ((const float2*)src)[i];
    uint16_t h0, l0, h1, l1;
    split_h(v.x, h0, l0);
    split_h(v.y, h1, l1);
    g_Sh[off + i] = (uint32_t)h0 | ((uint32_t)h1 << 16);
    g_Sl[off + i] = (uint32_t)l0 | ((uint32_t)l1 << 16);
}

__global__ void k_split_cb(const float* __restrict__ src, int npairs) {
    int i = blockIdx.x * blockDim.x + threadIdx.x;
    if (i >= npairs) return;
    float2 v = ((const float2*)src)[i];
    uint16_t h0, l0, h1, l1;
    split_h(v.x, h0, l0);
    split_h(v.y, h1, l1);
    g_Ch[i] = (uint32_t)h0 | ((uint32_t)h1 << 16);
    g_Cl[i] = (uint32_t)l0 | ((uint32_t)l1 << 16);
}

// transpose [K][N] fp32 -> [N][K] fp16 h/l  (which: 0 = W_s, 1 = W_p)
__global__ void k_split_tr(const float* __restrict__ src, int K, int N, int which) {
    __shared__ float ts[32][33];
    int tx = threadIdx.x, ty = threadIdx.y;
    int n0 = blockIdx.x * 32, k0 = blockIdx.y * 32;
    #pragma unroll
    for (int r = 0; r < 4; r++)
        ts[ty + 8 * r][tx] = src[(size_t)(k0 + ty + 8 * r) * N + n0 + tx];
    __syncthreads();
    __half* dh = (__half*)(which ? g_Wph : g_Wsh);
    __half* dl = (__half*)(which ? g_Wpl : g_Wsl);
    #pragma unroll
    for (int r = 0; r < 4; r++) {
        int n = n0 + ty + 8 * r, k = k0 + tx;
        float v = ts[tx][ty + 8 * r];
        uint16_t h, l;
        split_h(v, h, l);
        dh[(size_t)n * K + k] = __ushort_as_half(h);
        dl[(size_t)n * K + k] = __ushort_as_half(l);
    }
}

// ---------------- fp16 split GEMM (ldmatrix inner loop) ----------------
// MODE 0: H = gelu(S @ Ws^T + b_s) -> g_Hh/g_Hl        CTA 64x256, warp 32x64
// MODE 1: latent = H @ Wp^T + b_p  -> latent + Lh/Ll   CTA 64x128, warp 32x32
// MODE 2: scores = latent . CB^T   -> partial argmin   CTA 64x256, warp 32x64
template <int MODE, int KT>
__global__ void __launch_bounds__(256, 2) gemm_f16(const float* __restrict__ bias) {
    extern __shared__ uint32_t smu[];
    constexpr int NCTA  = (MODE == 1) ? 128 : 256;
    constexpr int WN    = (MODE == 1) ? 32 : 64;
    constexpr int NNT   = WN / 8;
    constexpr int NPAIR = NNT / 2;
    constexpr int NSTG  = (MODE == 1) ? 4 : 2;
    constexpr int KW    = KT / 2;
    constexpr int NCH   = KT / 32;
    constexpr int ASZ   = 64 * 32;
    constexpr int BSZ   = NCTA * 32;
    constexpr int STG   = ASZ + BSZ;
    constexpr int BPT   = NCTA * 8 / 256;      // B cp.async per thread

    const uint32_t* Ah = (MODE == 0) ? g_Sh : (MODE == 1) ? g_Hh : g_Lh;
    const uint32_t* Al = (MODE == 0) ? g_Sl : (MODE == 1) ? g_Hl : g_Ll;
    const uint32_t* Bh = (MODE == 0) ? g_Wsh : (MODE == 1) ? g_Wph : g_Ch;
    const uint32_t* Bl = (MODE == 0) ? g_Wsl : (MODE == 1) ? g_Wpl : g_Cl;

    const int tid = threadIdx.x;
    const int wid = tid >> 5, lane = tid & 31;
    const int wm  = (wid & 1) * 32;
    const int wn  = (wid >> 1) * WN;
    const int lt  = lane & 3, lg = lane >> 2;

    const int m0 = blockIdx.y * 64, n0 = blockIdx.x * NCTA;
    const size_t arow0 = (MODE == 0) ? ((size_t)blockIdx.z * NROWS + m0) : (size_t)m0;
    const uint32_t sb = smem_u32(smu);

    // per-lane ldmatrix address components
    const int l7 = lane & 7;
    const int amrow0 = wm + l7 + 8 * ((lane >> 3) & 1);      // + 16*mt
    const uint32_t axk = ((lane >> 4) & 1) ^ l7;
    const int bnrow0 = wn + l7 + 8 * ((lane >> 4) & 1);      // + 16*p
    const uint32_t bxk = ((lane >> 3) & 1) ^ l7;

    float acc[2][NNT][4];
    #pragma unroll
    for (int i = 0; i < 2; i++)
        #pragma unroll
        for (int j = 0; j < NNT; j++)
            #pragma unroll
            for (int e = 0; e < 4; e++) acc[i][j][e] = 0.0f;

    auto copy_chunk = [&](int c, int stg) {
        const uint32_t dA = sb + stg * STG * 4;
        const uint32_t dB = dA + ASZ * 4;
        #pragma unroll
        for (int j = 0; j < 2; j++) {
            int u = tid + j * 256;
            int m = u >> 3, p = u & 7;
            const uint32_t* s = ((p < 4) ? Ah : Al)
                + (arow0 + m) * KW + c * 16 + (p & 3) * 4;
            uint32_t dst = dA + (m * 32 + ((p ^ (m & 7)) << 2)) * 4;
            CP16(dst, s);
        }
        #pragma unroll
        for (int j = 0; j < BPT; j++) {
            int u = tid + j * 256;
            int n = u >> 3, p = u & 7;
            const uint32_t* s = ((p < 4) ? Bh : Bl)
                + (size_t)(n0 + n) * KW + c * 16 + (p & 3) * 4;
            uint32_t dst = dB + (n * 32 + ((p ^ (n & 7)) << 2)) * 4;
            CP16(dst, s);
        }
    };

    auto compute = [&](int stg) {
        const uint32_t sA = sb + stg * STG * 4;
        const uint32_t sB = sA + ASZ * 4;
        const uint32_t aBase0 = sA + (amrow0)      * 128;
        const uint32_t aBase1 = sA + (amrow0 + 16) * 128;
        #pragma unroll
        for (int s = 0; s < 2; s++) {
            const uint32_t ch = 2 * s;
            const uint32_t cl = 2 * s + 4;
            uint32_t ah[2][4], al[2][4];
            ldm_x4(ah[0], aBase0 + ((ch ^ axk) << 4));
            ldm_x4(al[0], aBase0 + ((cl ^ axk) << 4));
            ldm_x4(ah[1], aBase1 + ((ch ^ axk) << 4));
            ldm_x4(al[1], aBase1 + ((cl ^ axk) << 4));
            #pragma unroll
            for (int p = 0; p < NPAIR; p++) {
                uint32_t bh[4], bl[4];
                const uint32_t bb = sB + (bnrow0 + 16 * p) * 128;
                ldm_x4(bh, bb + ((ch ^ bxk) << 4));
                ldm_x4(bl, bb + ((cl ^ bxk) << 4));
                #pragma unroll
                for (int mt = 0; mt < 2; mt++) {
                    mma16(acc[mt][2 * p],     ah[mt], bh);
                    mma16(acc[mt][2 * p],     ah[mt], bl);
                    mma16(acc[mt][2 * p],     al[mt], bh);
                    mma16(acc[mt][2 * p + 1], ah[mt], bh + 2);
                    mma16(acc[mt][2 * p + 1], ah[mt], bl + 2);
                    mma16(acc[mt][2 * p + 1], al[mt], bh + 2);
                }
            }
        }
    };

    // ---- prologue ----
    #pragma unroll
    for (int c = 0; c < NSTG - 1 && c < NCH; c++) { copy_chunk(c, c); CP_COMMIT(); }

    // ---- mainloop ----
    for (int c = 0; c < NCH; c++) {
        cp_wait<NSTG - 2>();
        __syncthreads();
        const int cn = c + NSTG - 1;
        if (cn < NCH) copy_chunk(cn, cn & (NSTG - 1));
        CP_COMMIT();
        compute(c & (NSTG - 1));
    }

    // ---- epilogue ----
    if (MODE == 0) {
        const int zoff = blockIdx.z ? EDIM : 0;
        #pragma unroll
        for (int mt = 0; mt < 2; mt++)
            #pragma unroll
            for (int h = 0; h < 2; h++) {
                const int row = m0 + wm + mt * 16 + lg + h * 8;
                #pragma unroll
                for (int nt = 0; nt < NNT; nt++) {
                    const int col = wn + nt * 8 + 2 * lt;
                    float g0 = gelu_tanh(acc[mt][nt][h * 2 + 0] + bias[n0 + col]);
                    float g1 = gelu_tanh(acc[mt][nt][h * 2 + 1] + bias[n0 + col + 1]);
                    uint16_t h0, l0, h1, l1;
                    split_h(g0, h0, l0);
                    split_h(g1, h1, l1);
                    size_t cw = (size_t)row * (2 * EDIM / 2) + ((zoff + n0 + col) >> 1);
                    g_Hh[cw] = (uint32_t)h0 | ((uint32_t)h1 << 16);
                    g_Hl[cw] = (uint32_t)l0 | ((uint32_t)l1 << 16);
                }
            }
    } else if (MODE == 1) {
        #pragma unroll
        for (int mt = 0; mt < 2; mt++)
            #pragma unroll
            for (int h = 0; h < 2; h++) {
                const int row = m0 + wm + mt * 16 + lg + h * 8;
                #pragma unroll
                for (int nt = 0; nt < NNT; nt++) {
                    const int col = wn + nt * 8 + 2 * lt;
                    float v0 = acc[mt][nt][h * 2 + 0] + bias[n0 + col];
                    float v1 = acc[mt][nt][h * 2 + 1] + bias[n0 + col + 1];
                    float2 o; o.x = v0; o.y = v1;
                    *(float2*)(g_latent + (size_t)row * CDDIM + n0 + col) = o;
                    uint16_t h0, l0, h1, l1;
                    split_h(v0, h0, l0);
                    split_h(v1, h1, l1);
                    size_t cw = (size_t)row * (CDDIM / 2) + ((n0 + col) >> 1);
                    g_Lh[cw] = (uint32_t)h0 | ((uint32_t)h1 << 16);
                    g_Ll[cw] = (uint32_t)l0 | ((uint32_t)l1 << 16);
                }
            }
    } else {
        // per-warp partial argmin over its 64 codes
        #pragma unroll
        for (int mt = 0; mt < 2; mt++)
            #pragma unroll
            for (int h = 0; h < 2; h++) {
                const int row = m0 + wm + mt * 16 + lg + h * 8;
                float best = INFINITY; int bi = 0;
                #pragma unroll
                for (int nt = 0; nt < NNT; nt++)
                    #pragma unroll
                    for (int e = 0; e < 2; e++) {
                        const int col = n0 + wn + nt * 8 + 2 * lt + e;
                        float s = g_cnorm[col] - 2.0f * acc[mt][nt][h * 2 + e];
                        if (s < best) { best = s; bi = col; }
                    }
                #pragma unroll
                for (int msk = 1; msk <= 2; msk <<= 1) {
                    float ov = __shfl_xor_sync(0xffffffffu, best, msk);
                    int   oi = __shfl_xor_sync(0xffffffffu, bi,   msk);
                    if (ov < best || (ov == best && oi < bi)) { best = ov; bi = oi; }
                }
                if (lt == 0) {
                    // 16 slots/row: blockIdx.x (0..3) * 4 + warp-n (0..3)
                    g_pval[(size_t)row * 16 + blockIdx.x * 4 + (wid >> 1)] = best;
                    g_pidx[(size_t)row * 16 + blockIdx.x * 4 + (wid >> 1)] = bi;
                }
            }
    }
}

// ---------------- finalize ----------------
__global__ __launch_bounds__(256) void k_final(const float* __restrict__ CB,
                                               float* __restrict__ out, int full) {
    const int warp = threadIdx.x >> 5, lane = threadIdx.x & 31;
    const int row = blockIdx.x * 8 + warp;

    float v = INFINITY; int ii = 0x7fffffff;
    if (lane < 16) { v = g_pval[(size_t)row * 16 + lane]; ii = g_pidx[(size_t)row * 16 + lane]; }
    #pragma unroll
    for (int off = 16; off > 0; off >>= 1) {
        float ov = __shfl_down_sync(0xffffffffu, v, off);
        int   oi = __shfl_down_sync(0xffffffffu, ii, off);
        if (ov < v || (ov == v && oi < ii)) { v = ov; ii = oi; }
    }
    int idx = __shfl_sync(0xffffffffu, ii, 0);

    float ls = 0.0f;
    for (int j = lane; j < CDDIM; j += 32) {
        float c = CB[(size_t)idx * CDDIM + j];
        float l = g_latent[(size_t)row * CDDIM + j];
        out[OFF_Q + (size_t)row * CDDIM + j] = c;
        float d = c - l; ls += d * d;
    }
    #pragma unroll
    for (int off = 16; off > 0; off >>= 1)
        ls += __shfl_down_sync(0xffffffffu, ls, off);
    if (lane == 0) {
        atomicAdd(&g_loss_sum, ls);
        atomicAdd(&g_counts[idx], 1);
    }
    if (full) {
        float* enc = out + OFF_ENC + (size_t)row * NCODE;
        for (int j = lane; j < NCODE; j += 32) enc[j] = (j == idx) ? 1.0f : 0.0f;
        if (lane == 0) out[OFF_IDX + row] = (float)idx;
    }
}

__global__ void k_scalar(float* __restrict__ out) {
    __shared__ float sh[256];
    int t = threadIdx.x;
    float e = 0.0f;
    for (int c = t; c < NCODE; c += 256) {
        float p = (float)g_counts[c] * (1.0f / (float)NROWS);
        e += p * logf(p + 1e-10f);
    }
    sh[t] = e;
    __syncthreads();
    for (int s = 128; s > 0; s >>= 1) {
        if (t < s) sh[t] += sh[t + s];
        __syncthreads();
    }
    if (t == 0) {
        out[OFF_LOSS] = 0.25f * g_loss_sum / ((float)NROWS * (float)CDDIM);
        out[OFF_PERP] = expf(-sh[0]);
    }
}

// ---------------- launch ----------------
extern "C" void kernel_launch(void* const* d_in, const int* in_sizes, int n_in,
                              void* d_out, int out_size) {
    const float* states      = (const float*)d_in[0];
    const float* next_states = (const float*)d_in[1];
    const float* W_s         = (const float*)d_in[2];
    const float* b_s         = (const float*)d_in[3];
    const float* W_p         = (const float*)d_in[4];
    const float* b_p         = (const float*)d_in[5];
    const float* codebook    = (const float*)d_in[6];
    float* out = (float*)d_out;
    int full = (out_size >= OFF_ENC) ? 1 : 0;

    // smem: wide (MODE0/2): 2 * (64*32 + 256*32) * 4 = 81920 B
    //       narrow (MODE1): 4 * (64*32 + 128*32) * 4 = 98304 B
    constexpr int SM_W = 2 * (64 * 32 + 256 * 32) * 4;
    constexpr int SM_1 = 4 * (64 * 32 + 128 * 32) * 4;
    cudaFuncSetAttribute(gemm_f16<0, DDIM>,
                         cudaFuncAttributeMaxDynamicSharedMemorySize, SM_W);
    cudaFuncSetAttribute(gemm_f16<1, 2 * EDIM>,
                         cudaFuncAttributeMaxDynamicSharedMemorySize, SM_1);
    cudaFuncSetAttribute(gemm_f16<2, CDDIM>,
                         cudaFuncAttributeMaxDynamicSharedMemorySize, SM_W);

    k_prep<<<4, 256>>>(codebook);

    const int spairs = NROWS * DDIM / 2;
    k_split_rm<<<spairs / 256, 256>>>(states, 0, spairs);
    k_split_rm<<<spairs / 256, 256>>>(next_states, (uint32_t)spairs, spairs);
    k_split_tr<<<dim3(EDIM / 32, DDIM / 32), dim3(32, 8)>>>(W_s, DDIM, EDIM, 0);
    k_split_tr<<<dim3(CDDIM / 32, 2 * EDIM / 32), dim3(32, 8)>>>(W_p, 2 * EDIM, CDDIM, 1);
    k_split_cb<<<NCODE * CDDIM / 2 / 256, 256>>>(codebook, NCODE * CDDIM / 2);

    // encoder: M=8192, N=2048, K=1024 (two inputs via grid.z) -> Hh/Hl
    gemm_f16<0, DDIM><<<dim3(EDIM / 256, NROWS / 64, 2), 256, SM_W>>>(b_s);
    // policy head: M=8192, N=256, K=4096 -> latent fp32 + fp16 h/l
    gemm_f16<1, 2 * EDIM><<<dim3(CDDIM / 128, NROWS / 64, 1), 256, SM_1>>>(b_p);
    // scores: M=8192, N=1024 codes, K=256 (fp16 split)
    gemm_f16<2, CDDIM><<<dim3(NCODE / 256, NROWS / 64, 1), 256, SM_W>>>(nullptr);

    k_final<<<NROWS / 8, 256>>>(codebook, out, full);
    if (full) k_scalar<<<1, 256>>>(out);
}